// round 3
// baseline (speedup 1.0000x reference)
#include <cuda_runtime.h>

#define B_    32
#define HH    56
#define DIMC  384
#define NH    12
#define HD    32
#define L_    49
#define BW    2048
#define TOK   (B_*HH*HH)            // 100352
#define SCALE 0.17677669529663687f  // 32^-0.5

// Scratch (static device arrays: allocation-free per harness rules)
__device__ float g_q[BW*NH*L_*HD];
__device__ float g_k[BW*NH*L_*HD];
__device__ float g_v[BW*NH*L_*HD];
__device__ float g_o[TOK*DIMC];

// ---------------------------------------------------------------------------
// GEMM: C[M,N] = A[M,384] @ W[384,N] + bias, with mode-specific epilogue
//  MODE 0: q proj   -> g_q (window-partitioned layout), scaled by SCALE
//  MODE 1: kv proj  -> g_k / g_v (window-partitioned)
//  MODE 2: out proj -> d_out (linear), A taken from g_o
// ---------------------------------------------------------------------------
#define BM 128
#define BN 128
#define BK 16

template<int MODE>
__global__ __launch_bounds__(256) void gemm_kernel(
    const float* __restrict__ A, const float* __restrict__ Wt,
    const float* __restrict__ bias, float* __restrict__ Cout, int N)
{
    __shared__ float sA[BK][BM + 4];   // transposed A tile, padded
    __shared__ float sB[BK][BN];

    const float* Aptr = (MODE == 2) ? (const float*)g_o : A;

    int m0 = blockIdx.x * BM;
    int n0 = blockIdx.y * BN;
    int tid = threadIdx.x;
    int tm = tid >> 4, tn = tid & 15;

    float acc[8][8] = {};

    for (int kt = 0; kt < 384; kt += BK) {
        // Load A tile (transposed into smem)
        #pragma unroll
        for (int l = 0; l < 2; l++) {
            int e = tid + l * 256;
            int r = e >> 2, c4 = (e & 3) * 4;
            float4 v = *(const float4*)&Aptr[(size_t)(m0 + r) * 384 + kt + c4];
            sA[c4 + 0][r] = v.x; sA[c4 + 1][r] = v.y;
            sA[c4 + 2][r] = v.z; sA[c4 + 3][r] = v.w;
        }
        // Load B tile
        #pragma unroll
        for (int l = 0; l < 2; l++) {
            int e = tid + l * 256;
            int k = e >> 5, n4 = (e & 31) * 4;
            *(float4*)&sB[k][n4] = *(const float4*)&Wt[(size_t)(kt + k) * N + n0 + n4];
        }
        __syncthreads();
        #pragma unroll
        for (int k = 0; k < BK; k++) {
            float a[8], b[8];
            *(float4*)&a[0] = *(float4*)&sA[k][tm * 8];
            *(float4*)&a[4] = *(float4*)&sA[k][tm * 8 + 4];
            *(float4*)&b[0] = *(float4*)&sB[k][tn * 8];
            *(float4*)&b[4] = *(float4*)&sB[k][tn * 8 + 4];
            #pragma unroll
            for (int u = 0; u < 8; u++)
                #pragma unroll
                for (int v = 0; v < 8; v++)
                    acc[u][v] += a[u] * b[v];
        }
        __syncthreads();
    }

    // Epilogue
    #pragma unroll
    for (int u = 0; u < 8; u++) {
        int m = m0 + tm * 8 + u;
        int bb = m / 3136; int rem = m % 3136;
        int y = rem / 56;  int x = rem % 56;
        int win = bb * 64 + (y / 7) * 8 + (x / 7);
        int l   = (y % 7) * 7 + (x % 7);
        #pragma unroll
        for (int v = 0; v < 8; v++) {
            int col = n0 + tn * 8 + v;
            float val = acc[u][v] + bias[col];
            if (MODE == 0) {
                int h = col >> 5, d = col & 31;
                g_q[(((size_t)win * NH + h) * L_ + l) * HD + d] = val * SCALE;
            } else if (MODE == 1) {
                int c = (col < 384) ? col : col - 384;
                int h = c >> 5, d = c & 31;
                float* dst = (col < 384) ? g_k : g_v;
                dst[(((size_t)win * NH + h) * L_ + l) * HD + d] = val;
            } else {
                Cout[(size_t)m * 384 + col] = val;
            }
        }
    }
}

// ---------------------------------------------------------------------------
// Fused windowed attention: one block = (1 head, 4 windows).
// q/k/v + full 49x49 logits per window resident in smem; RPE staged in
// 7-row i-tiles (amortized over the 4 windows).
// ---------------------------------------------------------------------------
#define WB 4
#define CP 36                         // padded channel dim (bank-conflict-free f4)
#define K_OFF  7056
#define V_OFF  14112
#define LO_OFF 21168                  // logits [4][49][49] = 9604
#define R_OFF  30772
#define RQ_SZ  (7*49*CP)              // 12348
#define SMEM_FLOATS (R_OFF + 2*RQ_SZ) // 55468 -> 221,872 bytes

__global__ __launch_bounds__(256) void attn_kernel(const float* __restrict__ rpe)
{
    extern __shared__ float sm[];
    float* sQ  = sm;
    float* sK  = sm + K_OFF;
    float* sV  = sm + V_OFF;
    float* sL  = sm + LO_OFF;
    float* sQR = sm + R_OFF;            // q_rpe * SCALE   [7][49][CP]
    float* sKR = sm + R_OFF + RQ_SZ;    // k_rpe           [7][49][CP]

    int h   = blockIdx.y;
    int wg  = blockIdx.x;
    int tid = threadIdx.x;

    // ---- load q,k,v for 4 windows (coalesced float4) ----
    for (int e = tid; e < WB * 49 * 8; e += 256) {
        int w = e / 392, rem = e % 392;
        int row = rem >> 3, c4 = (rem & 7) * 4;
        size_t gb = ((((size_t)(wg * WB + w)) * NH + h) * L_ + row) * HD + c4;
        int si = w * (49 * CP) + row * CP + c4;
        *(float4*)&sQ[si] = *(const float4*)&g_q[gb];
        *(float4*)&sK[si] = *(const float4*)&g_k[gb];
        *(float4*)&sV[si] = *(const float4*)&g_v[gb];
    }
    __syncthreads();

    // ---- Phase A: logits = q·k + q·k_rpe + k·(q_rpe*SCALE) ----
    for (int i0 = 0; i0 < 49; i0 += 7) {
        for (int e = tid; e < 7 * 49 * 8; e += 256) {
            int p = e >> 3, c4 = (e & 7) * 4;
            int ii = p / 49, j = p % 49;
            int i = i0 + ii;
            int idx = (i / 7 - j / 7 + 6) * 13 + (i % 7 - j % 7 + 6);
            const float* src = rpe + (size_t)idx * 1152 + h * 96 + c4;
            float4 a  = *(const float4*)src;          // q_rpe slice
            float4 kk = *(const float4*)(src + 32);   // k_rpe slice
            a.x *= SCALE; a.y *= SCALE; a.z *= SCALE; a.w *= SCALE;
            int so = ii * (49 * CP) + j * CP + c4;
            *(float4*)&sQR[so] = a;
            *(float4*)&sKR[so] = kk;
        }
        __syncthreads();
        for (int t = tid; t < 7 * 49; t += 256) {
            int ii = t / 49, j = t % 49;
            int i = i0 + ii;
            float accw[WB] = {0.f, 0.f, 0.f, 0.f};
            #pragma unroll
            for (int c4 = 0; c4 < 32; c4 += 4) {
                float4 kr = *(float4*)&sKR[ii * (49 * CP) + j * CP + c4];
                float4 qr = *(float4*)&sQR[ii * (49 * CP) + j * CP + c4];
                #pragma unroll
                for (int wdx = 0; wdx < WB; wdx++) {
                    float4 qv = *(float4*)&sQ[wdx * (49 * CP) + i * CP + c4];
                    float4 kv = *(float4*)&sK[wdx * (49 * CP) + j * CP + c4];
                    float s = 0.f;
                    s += qv.x * (kv.x + kr.x) + kv.x * qr.x;
                    s += qv.y * (kv.y + kr.y) + kv.y * qr.y;
                    s += qv.z * (kv.z + kr.z) + kv.z * qr.z;
                    s += qv.w * (kv.w + kr.w) + kv.w * qr.w;
                    accw[wdx] += s;
                }
            }
            #pragma unroll
            for (int wdx = 0; wdx < WB; wdx++)
                sL[wdx * 2401 + i * 49 + j] = accw[wdx];
        }
        __syncthreads();
    }

    // ---- Phase B: softmax over each 49-row ----
    for (int r = tid; r < WB * 49; r += 256) {
        float* row = &sL[(r / 49) * 2401 + (r % 49) * 49];
        float mx = row[0];
        #pragma unroll 7
        for (int j = 1; j < 49; j++) mx = fmaxf(mx, row[j]);
        float s = 0.f;
        #pragma unroll 7
        for (int j = 0; j < 49; j++) { float e = __expf(row[j] - mx); row[j] = e; s += e; }
        float inv = 1.f / s;
        #pragma unroll 7
        for (int j = 0; j < 49; j++) row[j] *= inv;
    }
    __syncthreads();

    // ---- Phase C: out = P @ (v + v_rpe), write spatial layout for proj GEMM ----
    float* sVR = sQR;   // reuse rpe buffer
    for (int i0 = 0; i0 < 49; i0 += 7) {
        for (int e = tid; e < 7 * 49 * 8; e += 256) {
            int p = e >> 3, c4 = (e & 7) * 4;
            int ii = p / 49, j = p % 49;
            int i = i0 + ii;
            int idx = (i / 7 - j / 7 + 6) * 13 + (i % 7 - j % 7 + 6);
            const float* src = rpe + (size_t)idx * 1152 + h * 96 + 64 + c4;
            *(float4*)&sVR[ii * (49 * CP) + j * CP + c4] = *(const float4*)src;
        }
        __syncthreads();
        for (int t = tid; t < WB * 7 * 8; t += 256) {
            int w = t / 56, rr = t % 56;
            int ii = rr >> 3, c4 = (rr & 7) * 4;
            int i = i0 + ii;
            float4 acc = {0.f, 0.f, 0.f, 0.f};
            const float* prow = &sL[w * 2401 + i * 49];
            #pragma unroll 7
            for (int j = 0; j < 49; j++) {
                float p = prow[j];
                float4 vv = *(float4*)&sV[w * (49 * CP) + j * CP + c4];
                float4 vr = *(float4*)&sVR[ii * (49 * CP) + j * CP + c4];
                acc.x += p * (vv.x + vr.x); acc.y += p * (vv.y + vr.y);
                acc.z += p * (vv.z + vr.z); acc.w += p * (vv.w + vr.w);
            }
            int win = wg * WB + w;
            int bb = win >> 6, wi = (win >> 3) & 7, wj = win & 7;
            int y = wi * 7 + i / 7, x = wj * 7 + i % 7;
            size_t rowg = ((size_t)bb * 56 + y) * 56 + x;
            *(float4*)&g_o[rowg * 384 + h * 32 + c4] = acc;
        }
        __syncthreads();
    }
}

// ---------------------------------------------------------------------------
extern "C" void kernel_launch(void* const* d_in, const int* in_sizes, int n_in,
                              void* d_out, int out_size)
{
    const float* x   = (const float*)d_in[0];
    const float* ctx = (const float*)d_in[1];
    const float* rpe = (const float*)d_in[2];
    const float* qw  = (const float*)d_in[3];
    const float* qb  = (const float*)d_in[4];
    const float* kvw = (const float*)d_in[5];
    const float* kvb = (const float*)d_in[6];
    const float* pw  = (const float*)d_in[7];
    const float* pb  = (const float*)d_in[8];
    float* out = (float*)d_out;

    cudaFuncSetAttribute(attn_kernel, cudaFuncAttributeMaxDynamicSharedMemorySize,
                         SMEM_FLOATS * 4);

    gemm_kernel<0><<<dim3(TOK / BM, 384 / BN), 256>>>(x,   qw,  qb,  nullptr, 384);
    gemm_kernel<1><<<dim3(TOK / BM, 768 / BN), 256>>>(ctx, kvw, kvb, nullptr, 768);
    attn_kernel<<<dim3(BW / WB, NH), 256, SMEM_FLOATS * 4>>>(rpe);
    gemm_kernel<2><<<dim3(TOK / BM, 384 / BN), 256>>>(nullptr, pw, pb, out, 384);
}

// round 4
// speedup vs baseline: 1.1009x; 1.1009x over previous
#include <cuda_runtime.h>

#define B_    32
#define HH    56
#define DIMC  384
#define NH    12
#define HD    32
#define L_    49
#define BW    2048
#define TOK   (B_*HH*HH)            // 100352
#define SCALE 0.17677669529663687f  // 32^-0.5

// Scratch (static device arrays: allocation-free per harness rules)
__device__ float g_q[BW*NH*L_*HD];
__device__ float g_k[BW*NH*L_*HD];
__device__ float g_v[BW*NH*L_*HD];
__device__ float g_o[TOK*DIMC];

// ---------------------------------------------------------------------------
// GEMM: C[M,N] = A[M,384] @ W[384,N] + bias, double-buffered smem pipeline.
//  MODE 0: q proj   -> g_q (window-partitioned layout), scaled by SCALE
//  MODE 1: kv proj  -> g_k / g_v (window-partitioned)
//  MODE 2: out proj -> d_out (linear), A taken from g_o
// ---------------------------------------------------------------------------
#define BM 128
#define BN 128
#define BK 16
#define NSTAGE (384/BK)   // 24

template<int MODE>
__global__ __launch_bounds__(256, 2) void gemm_kernel(
    const float* __restrict__ A, const float* __restrict__ Wt,
    const float* __restrict__ bias, float* __restrict__ Cout, int N)
{
    __shared__ float sA[2][BK][BM + 4];   // transposed A tile, padded
    __shared__ float sB[2][BK][BN];

    const float* Aptr = (MODE == 2) ? (const float*)g_o : A;

    int m0 = blockIdx.x * BM;
    int n0 = blockIdx.y * BN;
    int tid = threadIdx.x;
    int tm = tid >> 4, tn = tid & 15;

    // Per-thread load coordinates (fixed across stages)
    int ar0 = tid >> 2,          ac = (tid & 3) * 4;       // A rows 0..63 / 64..127
    int ar1 = (tid + 256) >> 2;
    int bk0 = tid >> 5,          bn = (tid & 31) * 4;      // B k 0..7 / 8..15
    int bk1 = bk0 + 8;

    const float* Ar0 = Aptr + (size_t)(m0 + ar0) * 384 + ac;
    const float* Ar1 = Aptr + (size_t)(m0 + ar1) * 384 + ac;
    const float* Br0 = Wt + (size_t)bk0 * N + n0 + bn;
    const float* Br1 = Wt + (size_t)bk1 * N + n0 + bn;

    float4 pa0, pa1, pb0, pb1;

    // prologue: stage 0
    pa0 = *(const float4*)(Ar0);
    pa1 = *(const float4*)(Ar1);
    pb0 = *(const float4*)(Br0);
    pb1 = *(const float4*)(Br1);
    sA[0][ac + 0][ar0] = pa0.x; sA[0][ac + 1][ar0] = pa0.y;
    sA[0][ac + 2][ar0] = pa0.z; sA[0][ac + 3][ar0] = pa0.w;
    sA[0][ac + 0][ar1] = pa1.x; sA[0][ac + 1][ar1] = pa1.y;
    sA[0][ac + 2][ar1] = pa1.z; sA[0][ac + 3][ar1] = pa1.w;
    *(float4*)&sB[0][bk0][bn] = pb0;
    *(float4*)&sB[0][bk1][bn] = pb1;
    __syncthreads();

    float acc[8][8] = {};
    int buf = 0;

    for (int s = 0; s < NSTAGE; s++) {
        if (s < NSTAGE - 1) {
            int kt = (s + 1) * BK;
            pa0 = *(const float4*)(Ar0 + kt);
            pa1 = *(const float4*)(Ar1 + kt);
            pb0 = *(const float4*)(Br0 + (size_t)kt * N);
            pb1 = *(const float4*)(Br1 + (size_t)kt * N);
        }
        const float (*cA)[BM + 4] = sA[buf];
        const float (*cB)[BN]     = sB[buf];
        #pragma unroll
        for (int k = 0; k < BK; k++) {
            float a[8], b[8];
            *(float4*)&a[0] = *(const float4*)&cA[k][tm * 8];
            *(float4*)&a[4] = *(const float4*)&cA[k][tm * 8 + 4];
            *(float4*)&b[0] = *(const float4*)&cB[k][tn * 8];
            *(float4*)&b[4] = *(const float4*)&cB[k][tn * 8 + 4];
            #pragma unroll
            for (int u = 0; u < 8; u++)
                #pragma unroll
                for (int v = 0; v < 8; v++)
                    acc[u][v] += a[u] * b[v];
        }
        if (s < NSTAGE - 1) {
            int nb = buf ^ 1;
            sA[nb][ac + 0][ar0] = pa0.x; sA[nb][ac + 1][ar0] = pa0.y;
            sA[nb][ac + 2][ar0] = pa0.z; sA[nb][ac + 3][ar0] = pa0.w;
            sA[nb][ac + 0][ar1] = pa1.x; sA[nb][ac + 1][ar1] = pa1.y;
            sA[nb][ac + 2][ar1] = pa1.z; sA[nb][ac + 3][ar1] = pa1.w;
            *(float4*)&sB[nb][bk0][bn] = pb0;
            *(float4*)&sB[nb][bk1][bn] = pb1;
            __syncthreads();
            buf = nb;
        }
    }

    // Epilogue
    #pragma unroll
    for (int u = 0; u < 8; u++) {
        int m = m0 + tm * 8 + u;
        int bb = m / 3136; int rem = m % 3136;
        int y = rem / 56;  int x = rem % 56;
        int win = bb * 64 + (y / 7) * 8 + (x / 7);
        int l   = (y % 7) * 7 + (x % 7);
        #pragma unroll
        for (int v = 0; v < 8; v++) {
            int col = n0 + tn * 8 + v;
            float val = acc[u][v] + bias[col];
            if (MODE == 0) {
                int h = col >> 5, d = col & 31;
                g_q[(((size_t)win * NH + h) * L_ + l) * HD + d] = val * SCALE;
            } else if (MODE == 1) {
                int c = (col < 384) ? col : col - 384;
                int h = c >> 5, d = c & 31;
                float* dst = (col < 384) ? g_k : g_v;
                dst[(((size_t)win * NH + h) * L_ + l) * HD + d] = val;
            } else {
                Cout[(size_t)m * 384 + col] = val;
            }
        }
    }
}

// ---------------------------------------------------------------------------
// Fused windowed attention: one block = (1 head, 4 windows).
// q/k/v + full 49x49 logits per window resident in smem; RPE staged in
// 7-row i-tiles (amortized over the 4 windows).
// Phase A uses j-pair register blocking: thread covers (ii, j, j+25),
// amortizing the q vector over both j's.
// ---------------------------------------------------------------------------
#define WB 4
#define CP 36                         // padded channel dim (bank-conflict-free f4)
#define K_OFF  7056
#define V_OFF  14112
#define LO_OFF 21168                  // logits [4][49][49] = 9604
#define R_OFF  30772
#define RQ_SZ  (7*49*CP)              // 12348
#define SMEM_FLOATS (R_OFF + 2*RQ_SZ) // 55468 -> 221,872 bytes

__global__ __launch_bounds__(256) void attn_kernel(const float* __restrict__ rpe)
{
    extern __shared__ float sm[];
    float* sQ  = sm;
    float* sK  = sm + K_OFF;
    float* sV  = sm + V_OFF;
    float* sL  = sm + LO_OFF;
    float* sQR = sm + R_OFF;            // q_rpe * SCALE   [7][49][CP]
    float* sKR = sm + R_OFF + RQ_SZ;    // k_rpe           [7][49][CP]

    int h   = blockIdx.y;
    int wg  = blockIdx.x;
    int tid = threadIdx.x;

    // ---- load q,k,v for 4 windows (coalesced float4) ----
    for (int e = tid; e < WB * 49 * 8; e += 256) {
        int w = e / 392, rem = e % 392;
        int row = rem >> 3, c4 = (rem & 7) * 4;
        size_t gb = ((((size_t)(wg * WB + w)) * NH + h) * L_ + row) * HD + c4;
        int si = w * (49 * CP) + row * CP + c4;
        *(float4*)&sQ[si] = *(const float4*)&g_q[gb];
        *(float4*)&sK[si] = *(const float4*)&g_k[gb];
        *(float4*)&sV[si] = *(const float4*)&g_v[gb];
    }
    __syncthreads();

    // ---- Phase A: logits = q·k + q·k_rpe + k·(q_rpe*SCALE) ----
    for (int i0 = 0; i0 < 49; i0 += 7) {
        for (int e = tid; e < 7 * 49 * 8; e += 256) {
            int p = e >> 3, c4 = (e & 7) * 4;
            int ii = p / 49, j = p % 49;
            int i = i0 + ii;
            int idx = (i / 7 - j / 7 + 6) * 13 + (i % 7 - j % 7 + 6);
            const float* src = rpe + (size_t)idx * 1152 + h * 96 + c4;
            float4 a  = *(const float4*)src;          // q_rpe slice
            float4 kk = *(const float4*)(src + 32);   // k_rpe slice
            a.x *= SCALE; a.y *= SCALE; a.z *= SCALE; a.w *= SCALE;
            int so = ii * (49 * CP) + j * CP + c4;
            *(float4*)&sQR[so] = a;
            *(float4*)&sKR[so] = kk;
        }
        __syncthreads();
        if (tid < 175) {
            int ii = tid / 25, jp = tid % 25;
            int i  = i0 + ii;
            int j1 = jp, j2 = jp + 25;
            bool has2 = (j2 < 49);
            float accw[WB][2] = {};
            int rbase = ii * (49 * CP);
            #pragma unroll
            for (int c4 = 0; c4 < 32; c4 += 4) {
                float4 kr1 = *(float4*)&sKR[rbase + j1 * CP + c4];
                float4 qr1 = *(float4*)&sQR[rbase + j1 * CP + c4];
                float4 kr2, qr2;
                if (has2) {
                    kr2 = *(float4*)&sKR[rbase + j2 * CP + c4];
                    qr2 = *(float4*)&sQR[rbase + j2 * CP + c4];
                }
                #pragma unroll
                for (int wdx = 0; wdx < WB; wdx++) {
                    float4 qv = *(float4*)&sQ[wdx * (49 * CP) + i * CP + c4];
                    float4 kv = *(float4*)&sK[wdx * (49 * CP) + j1 * CP + c4];
                    float s = 0.f;
                    s += qv.x * (kv.x + kr1.x) + kv.x * qr1.x;
                    s += qv.y * (kv.y + kr1.y) + kv.y * qr1.y;
                    s += qv.z * (kv.z + kr1.z) + kv.z * qr1.z;
                    s += qv.w * (kv.w + kr1.w) + kv.w * qr1.w;
                    accw[wdx][0] += s;
                    if (has2) {
                        float4 kw = *(float4*)&sK[wdx * (49 * CP) + j2 * CP + c4];
                        float t = 0.f;
                        t += qv.x * (kw.x + kr2.x) + kw.x * qr2.x;
                        t += qv.y * (kw.y + kr2.y) + kw.y * qr2.y;
                        t += qv.z * (kw.z + kr2.z) + kw.z * qr2.z;
                        t += qv.w * (kw.w + kr2.w) + kw.w * qr2.w;
                        accw[wdx][1] += t;
                    }
                }
            }
            #pragma unroll
            for (int wdx = 0; wdx < WB; wdx++) {
                sL[wdx * 2401 + i * 49 + j1] = accw[wdx][0];
                if (has2) sL[wdx * 2401 + i * 49 + j2] = accw[wdx][1];
            }
        }
        __syncthreads();
    }

    // ---- Phase B: softmax over each 49-row ----
    for (int r = tid; r < WB * 49; r += 256) {
        float* row = &sL[(r / 49) * 2401 + (r % 49) * 49];
        float mx = row[0];
        #pragma unroll 7
        for (int j = 1; j < 49; j++) mx = fmaxf(mx, row[j]);
        float s = 0.f;
        #pragma unroll 7
        for (int j = 0; j < 49; j++) { float e = __expf(row[j] - mx); row[j] = e; s += e; }
        float inv = 1.f / s;
        #pragma unroll 7
        for (int j = 0; j < 49; j++) row[j] *= inv;
    }
    __syncthreads();

    // ---- Phase C: out = P @ (v + v_rpe), write spatial layout for proj GEMM ----
    float* sVR = sQR;   // reuse rpe buffer
    for (int i0 = 0; i0 < 49; i0 += 7) {
        for (int e = tid; e < 7 * 49 * 8; e += 256) {
            int p = e >> 3, c4 = (e & 7) * 4;
            int ii = p / 49, j = p % 49;
            int i = i0 + ii;
            int idx = (i / 7 - j / 7 + 6) * 13 + (i % 7 - j % 7 + 6);
            const float* src = rpe + (size_t)idx * 1152 + h * 96 + 64 + c4;
            *(float4*)&sVR[ii * (49 * CP) + j * CP + c4] = *(const float4*)src;
        }
        __syncthreads();
        for (int t = tid; t < WB * 7 * 8; t += 256) {
            int w = t / 56, rr = t % 56;
            int ii = rr >> 3, c4 = (rr & 7) * 4;
            int i = i0 + ii;
            float4 acc = {0.f, 0.f, 0.f, 0.f};
            const float* prow = &sL[w * 2401 + i * 49];
            #pragma unroll 7
            for (int j = 0; j < 49; j++) {
                float p = prow[j];
                float4 vv = *(float4*)&sV[w * (49 * CP) + j * CP + c4];
                float4 vr = *(float4*)&sVR[ii * (49 * CP) + j * CP + c4];
                acc.x += p * (vv.x + vr.x); acc.y += p * (vv.y + vr.y);
                acc.z += p * (vv.z + vr.z); acc.w += p * (vv.w + vr.w);
            }
            int win = wg * WB + w;
            int bb = win >> 6, wi = (win >> 3) & 7, wj = win & 7;
            int y = wi * 7 + i / 7, x = wj * 7 + i % 7;
            size_t rowg = ((size_t)bb * 56 + y) * 56 + x;
            *(float4*)&g_o[rowg * 384 + h * 32 + c4] = acc;
        }
        __syncthreads();
    }
}

// ---------------------------------------------------------------------------
extern "C" void kernel_launch(void* const* d_in, const int* in_sizes, int n_in,
                              void* d_out, int out_size)
{
    const float* x   = (const float*)d_in[0];
    const float* ctx = (const float*)d_in[1];
    const float* rpe = (const float*)d_in[2];
    const float* qw  = (const float*)d_in[3];
    const float* qb  = (const float*)d_in[4];
    const float* kvw = (const float*)d_in[5];
    const float* kvb = (const float*)d_in[6];
    const float* pw  = (const float*)d_in[7];
    const float* pb  = (const float*)d_in[8];
    float* out = (float*)d_out;

    cudaFuncSetAttribute(attn_kernel, cudaFuncAttributeMaxDynamicSharedMemorySize,
                         SMEM_FLOATS * 4);

    gemm_kernel<0><<<dim3(TOK / BM, 384 / BN), 256>>>(x,   qw,  qb,  nullptr, 384);
    gemm_kernel<1><<<dim3(TOK / BM, 768 / BN), 256>>>(ctx, kvw, kvb, nullptr, 768);
    attn_kernel<<<dim3(BW / WB, NH), 256, SMEM_FLOATS * 4>>>(rpe);
    gemm_kernel<2><<<dim3(TOK / BM, 384 / BN), 256>>>(nullptr, pw, pb, out, 384);
}

// round 10
// speedup vs baseline: 1.3783x; 1.2520x over previous
#include <cuda_runtime.h>

#define B_    32
#define HH    56
#define DIMC  384
#define NH    12
#define HD    32
#define L_    49
#define BW    2048
#define TOK   (B_*HH*HH)            // 100352
#define SCALE 0.17677669529663687f  // 32^-0.5

// Scratch (static device arrays — identical footprint to the R4 pass)
__device__ float g_q[BW*NH*L_*HD];
__device__ float g_k[BW*NH*L_*HD];
__device__ float g_v[BW*NH*L_*HD];
__device__ float g_o[TOK*DIMC];

// ---------------------------------------------------------------------------
// GEMM (verbatim R4, known-good): C[M,N] = A[M,384] @ W[384,N] + bias
//  MODE 0: q proj -> g_q (window layout, xSCALE)  MODE 1: kv -> g_k/g_v
//  MODE 2: out proj -> d_out, A from g_o
// ---------------------------------------------------------------------------
#define BM 128
#define BN 128
#define BK 16
#define NSTAGE (384/BK)   // 24

template<int MODE>
__global__ __launch_bounds__(256, 2) void gemm_kernel(
    const float* __restrict__ A, const float* __restrict__ Wt,
    const float* __restrict__ bias, float* __restrict__ Cout, int N)
{
    __shared__ float sA[2][BK][BM + 4];
    __shared__ float sB[2][BK][BN];

    const float* Aptr = (MODE == 2) ? (const float*)g_o : A;

    int m0 = blockIdx.x * BM;
    int n0 = blockIdx.y * BN;
    int tid = threadIdx.x;
    int tm = tid >> 4, tn = tid & 15;

    int ar0 = tid >> 2,          ac = (tid & 3) * 4;
    int ar1 = (tid + 256) >> 2;
    int bk0 = tid >> 5,          bn = (tid & 31) * 4;
    int bk1 = bk0 + 8;

    const float* Ar0 = Aptr + (size_t)(m0 + ar0) * 384 + ac;
    const float* Ar1 = Aptr + (size_t)(m0 + ar1) * 384 + ac;
    const float* Br0 = Wt + (size_t)bk0 * N + n0 + bn;
    const float* Br1 = Wt + (size_t)bk1 * N + n0 + bn;

    float4 pa0, pa1, pb0, pb1;

    pa0 = *(const float4*)(Ar0);
    pa1 = *(const float4*)(Ar1);
    pb0 = *(const float4*)(Br0);
    pb1 = *(const float4*)(Br1);
    sA[0][ac + 0][ar0] = pa0.x; sA[0][ac + 1][ar0] = pa0.y;
    sA[0][ac + 2][ar0] = pa0.z; sA[0][ac + 3][ar0] = pa0.w;
    sA[0][ac + 0][ar1] = pa1.x; sA[0][ac + 1][ar1] = pa1.y;
    sA[0][ac + 2][ar1] = pa1.z; sA[0][ac + 3][ar1] = pa1.w;
    *(float4*)&sB[0][bk0][bn] = pb0;
    *(float4*)&sB[0][bk1][bn] = pb1;
    __syncthreads();

    float acc[8][8] = {};
    int buf = 0;

    for (int s = 0; s < NSTAGE; s++) {
        if (s < NSTAGE - 1) {
            int kt = (s + 1) * BK;
            pa0 = *(const float4*)(Ar0 + kt);
            pa1 = *(const float4*)(Ar1 + kt);
            pb0 = *(const float4*)(Br0 + (size_t)kt * N);
            pb1 = *(const float4*)(Br1 + (size_t)kt * N);
        }
        const float (*cA)[BM + 4] = sA[buf];
        const float (*cB)[BN]     = sB[buf];
        #pragma unroll
        for (int k = 0; k < BK; k++) {
            float a[8], b[8];
            *(float4*)&a[0] = *(const float4*)&cA[k][tm * 8];
            *(float4*)&a[4] = *(const float4*)&cA[k][tm * 8 + 4];
            *(float4*)&b[0] = *(const float4*)&cB[k][tn * 8];
            *(float4*)&b[4] = *(const float4*)&cB[k][tn * 8 + 4];
            #pragma unroll
            for (int u = 0; u < 8; u++)
                #pragma unroll
                for (int v = 0; v < 8; v++)
                    acc[u][v] += a[u] * b[v];
        }
        if (s < NSTAGE - 1) {
            int nb = buf ^ 1;
            sA[nb][ac + 0][ar0] = pa0.x; sA[nb][ac + 1][ar0] = pa0.y;
            sA[nb][ac + 2][ar0] = pa0.z; sA[nb][ac + 3][ar0] = pa0.w;
            sA[nb][ac + 0][ar1] = pa1.x; sA[nb][ac + 1][ar1] = pa1.y;
            sA[nb][ac + 2][ar1] = pa1.z; sA[nb][ac + 3][ar1] = pa1.w;
            *(float4*)&sB[nb][bk0][bn] = pb0;
            *(float4*)&sB[nb][bk1][bn] = pb1;
            __syncthreads();
            buf = nb;
        }
    }

    #pragma unroll
    for (int u = 0; u < 8; u++) {
        int m = m0 + tm * 8 + u;
        int bb = m / 3136; int rem = m % 3136;
        int y = rem / 56;  int x = rem % 56;
        int win = bb * 64 + (y / 7) * 8 + (x / 7);
        int l   = (y % 7) * 7 + (x % 7);
        #pragma unroll
        for (int v = 0; v < 8; v++) {
            int col = n0 + tn * 8 + v;
            float val = acc[u][v] + bias[col];
            if (MODE == 0) {
                int h = col >> 5, d = col & 31;
                g_q[(((size_t)win * NH + h) * L_ + l) * HD + d] = val * SCALE;
            } else if (MODE == 1) {
                int c = (col < 384) ? col : col - 384;
                int h = c >> 5, d = c & 31;
                float* dst = (col < 384) ? g_k : g_v;
                dst[(((size_t)win * NH + h) * L_ + l) * HD + d] = val;
            } else {
                Cout[(size_t)m * 384 + col] = val;
            }
        }
    }
}

// ---------------------------------------------------------------------------
// Fused windowed attention v2: one block = (1 head, 4 windows).
// The full 169-row per-head RPE table lives in smem (RPI value == table row),
// so there is NO per-i-tile re-gather from L2 and NO staging syncs.
// ---------------------------------------------------------------------------
#define WB 4
#define CP 36
#define TP 100                        // padded table row (96 floats + 4)
#define K_OFF  7056
#define V_OFF  14112
#define LO_OFF 21168                  // logits [4][49][49] = 9604
#define T_OFF  30772                  // table [169][TP] = 16900
#define SMEM_FLOATS (T_OFF + 169*TP)  // 47672 -> 190,688 bytes

__global__ __launch_bounds__(256) void attn_kernel(const float* __restrict__ rpe)
{
    extern __shared__ float sm[];
    float* sQ = sm;
    float* sK = sm + K_OFF;
    float* sV = sm + V_OFF;
    float* sL = sm + LO_OFF;
    float* sT = sm + T_OFF;           // [169][TP]: qr*SCALE | kr | vr

    int h   = blockIdx.y;
    int wg  = blockIdx.x;
    int tid = threadIdx.x;

    // ---- load q,k,v for 4 windows ----
    for (int e = tid; e < WB * 49 * 8; e += 256) {
        int w = e / 392, rem = e % 392;
        int row = rem >> 3, c4 = (rem & 7) * 4;
        size_t gb = ((((size_t)(wg * WB + w)) * NH + h) * L_ + row) * HD + c4;
        int si = w * (49 * CP) + row * CP + c4;
        *(float4*)&sQ[si] = *(const float4*)&g_q[gb];
        *(float4*)&sK[si] = *(const float4*)&g_k[gb];
        *(float4*)&sV[si] = *(const float4*)&g_v[gb];
    }
    // ---- load full per-head RPE table: 169 rows x 24 float4 ----
    for (int e = tid; e < 169 * 24; e += 256) {
        int row = e / 24, seg = e % 24;
        float4 v = *(const float4*)&rpe[(size_t)row * 1152 + h * 96 + seg * 4];
        if (seg < 8) { v.x *= SCALE; v.y *= SCALE; v.z *= SCALE; v.w *= SCALE; }
        *(float4*)&sT[row * TP + seg * 4] = v;
    }
    __syncthreads();

    // ---- Phase A: logits = q·k + q·k_rpe + k·(q_rpe*SCALE), flat loop ----
    for (int t = tid; t < 49 * 25; t += 256) {
        int i = t / 25, jp = t % 25;
        int j1 = jp, j2 = jp + 25;
        bool has2 = (jp < 24);
        int ir = i / 7, ic = i % 7;
        int b1 = ((ir - j1 / 7 + 6) * 13 + (ic - j1 % 7 + 6)) * TP;
        int b2 = ((ir - j2 / 7 + 6) * 13 + (ic - j2 % 7 + 6)) * TP;
        float accw[WB][2] = {};
        #pragma unroll
        for (int c4 = 0; c4 < 32; c4 += 4) {
            float4 qr1 = *(float4*)&sT[b1 + c4];
            float4 kr1 = *(float4*)&sT[b1 + 32 + c4];
            float4 qr2 = *(float4*)&sT[b2 + c4];
            float4 kr2 = *(float4*)&sT[b2 + 32 + c4];
            #pragma unroll
            for (int wdx = 0; wdx < WB; wdx++) {
                float4 qv = *(float4*)&sQ[wdx * (49 * CP) + i * CP + c4];
                float4 kv = *(float4*)&sK[wdx * (49 * CP) + j1 * CP + c4];
                float s = 0.f;
                s += qv.x * (kv.x + kr1.x) + kv.x * qr1.x;
                s += qv.y * (kv.y + kr1.y) + kv.y * qr1.y;
                s += qv.z * (kv.z + kr1.z) + kv.z * qr1.z;
                s += qv.w * (kv.w + kr1.w) + kv.w * qr1.w;
                accw[wdx][0] += s;
                if (has2) {
                    float4 kw = *(float4*)&sK[wdx * (49 * CP) + j2 * CP + c4];
                    float u = 0.f;
                    u += qv.x * (kw.x + kr2.x) + kw.x * qr2.x;
                    u += qv.y * (kw.y + kr2.y) + kw.y * qr2.y;
                    u += qv.z * (kw.z + kr2.z) + kw.z * qr2.z;
                    u += qv.w * (kw.w + kr2.w) + kw.w * qr2.w;
                    accw[wdx][1] += u;
                }
            }
        }
        #pragma unroll
        for (int wdx = 0; wdx < WB; wdx++) {
            sL[wdx * 2401 + i * 49 + j1] = accw[wdx][0];
            if (has2) sL[wdx * 2401 + i * 49 + j2] = accw[wdx][1];
        }
    }
    __syncthreads();

    // ---- Phase B: softmax over each 49-row ----
    for (int r = tid; r < WB * 49; r += 256) {
        float* row = &sL[(r / 49) * 2401 + (r % 49) * 49];
        float mx = row[0];
        #pragma unroll 7
        for (int j = 1; j < 49; j++) mx = fmaxf(mx, row[j]);
        float s = 0.f;
        #pragma unroll 7
        for (int j = 0; j < 49; j++) { float e = __expf(row[j] - mx); row[j] = e; s += e; }
        float inv = 1.f / s;
        #pragma unroll 7
        for (int j = 0; j < 49; j++) row[j] *= inv;
    }
    __syncthreads();

    // ---- Phase C: out = P @ (v + v_rpe), vr read straight from table ----
    for (int t = tid; t < WB * 49 * 8; t += 256) {
        int c4 = (t & 7) * 4;
        int rest = t >> 3;
        int i = rest % 49, w = rest / 49;
        int ir = i / 7, ic = i % 7;
        int base = ((ir + 6) * 13 + ic + 6) * TP + 64 + c4;
        float4 acc = {0.f, 0.f, 0.f, 0.f};
        const float* prow = &sL[w * 2401 + i * 49];
        #pragma unroll
        for (int j = 0; j < 49; j++) {
            float p = prow[j];
            float4 vv = *(float4*)&sV[w * (49 * CP) + j * CP + c4];
            float4 vr = *(float4*)&sT[base - ((j / 7) * 13 + j % 7) * TP];
            acc.x += p * (vv.x + vr.x); acc.y += p * (vv.y + vr.y);
            acc.z += p * (vv.z + vr.z); acc.w += p * (vv.w + vr.w);
        }
        int win = wg * WB + w;
        int bb = win >> 6, wi = (win >> 3) & 7, wj = win & 7;
        int y = wi * 7 + ir, x = wj * 7 + ic;
        size_t rowg = ((size_t)bb * 56 + y) * 56 + x;
        *(float4*)&g_o[rowg * 384 + h * 32 + c4] = acc;
    }
}

// ---------------------------------------------------------------------------
extern "C" void kernel_launch(void* const* d_in, const int* in_sizes, int n_in,
                              void* d_out, int out_size)
{
    const float* x   = (const float*)d_in[0];
    const float* ctx = (const float*)d_in[1];
    const float* rpe = (const float*)d_in[2];
    const float* qw  = (const float*)d_in[3];
    const float* qb  = (const float*)d_in[4];
    const float* kvw = (const float*)d_in[5];
    const float* kvb = (const float*)d_in[6];
    const float* pw  = (const float*)d_in[7];
    const float* pb  = (const float*)d_in[8];
    float* out = (float*)d_out;

    cudaFuncSetAttribute(attn_kernel, cudaFuncAttributeMaxDynamicSharedMemorySize,
                         SMEM_FLOATS * 4);

    gemm_kernel<0><<<dim3(TOK / BM, 384 / BN), 256>>>(x,   qw,  qb,  nullptr, 384);
    gemm_kernel<1><<<dim3(TOK / BM, 768 / BN), 256>>>(ctx, kvw, kvb, nullptr, 768);
    attn_kernel<<<dim3(BW / WB, NH), 256, SMEM_FLOATS * 4>>>(rpe);
    gemm_kernel<2><<<dim3(TOK / BM, 384 / BN), 256>>>(nullptr, pw, pb, out, 384);
}

// round 11
// speedup vs baseline: 1.7565x; 1.2744x over previous
#include <cuda_runtime.h>
#include <cuda_bf16.h>
#include <cstdint>

#define B_    32
#define HH    56
#define DIMC  384
#define NH    12
#define HD    32
#define L_    49
#define BW    2048
#define TOK   (B_*HH*HH)            // 100352
#define SCALE 0.17677669529663687f  // 32^-0.5

// Scratch (static device arrays — identical footprint to the R10 pass)
__device__ float g_q[BW*NH*L_*HD];
__device__ float g_k[BW*NH*L_*HD];
__device__ float g_v[BW*NH*L_*HD];
__device__ float g_o[TOK*DIMC];

// ---------------- helpers (value-only, nothing address-taken) ----------------
__device__ __forceinline__ uint32_t pack_bf16(float lo, float hi) {
    uint32_t r;
    asm("cvt.rn.bf16x2.f32 %0, %1, %2;" : "=r"(r) : "f"(hi), "f"(lo));
    return r;
}
__device__ __forceinline__ float bf16_rt(float x) {
    return __bfloat162float(__float2bfloat16(x));
}
#define MMA_BF16(d0, d1, d2, d3, a0, a1, a2, a3, b0, b1) \
    asm volatile("mma.sync.aligned.m16n8k16.row.col.f32.bf16.bf16.f32 " \
        "{%0,%1,%2,%3}, {%4,%5,%6,%7}, {%8,%9}, {%0,%1,%2,%3};" \
        : "+f"(d0), "+f"(d1), "+f"(d2), "+f"(d3) \
        : "r"(a0), "r"(a1), "r"(a2), "r"(a3), "r"(b0), "r"(b1))

// ---------------------------------------------------------------------------
// bf16 hi/lo mma GEMM: C[M,N] = A[M,384] @ W[384,N] + bias
// Per K16 chunk: acc += Ah·Wh + Al·Wh + Ah·Wl  (fp32 accumulate)
// fp32 loaded with R10's proven loader; conversion to pre-paired bf16x2
// fragments happens in-register; fragment extraction is plain LDS.32 from
// padded smem (pitch 12 / 136 words -> conflict-free). No cp.async/ldmatrix.
//  MODE 0: q proj -> g_q (window layout, xSCALE)  MODE 1: kv -> g_k/g_v
//  MODE 2: out proj -> d_out, A from g_o
// ---------------------------------------------------------------------------
#define KC 16
#define NCHK 24          // 384 / 16
#define GT 512
// smem word offsets (uint32 words). A pair-tile: [128][12] (8 data + 4 pad),
// W pair-tile: [8][136] (128 data + 8 pad). Two buffers.
#define W_AH 0
#define W_AL 1536
#define W_WH 3072
#define W_WL 4160
#define BUFW 5248
#define SM_TOT (2 * BUFW * 4)   // 41,984 bytes

#define CONV_STORE(b) do {                                                    \
    uint32_t bb_ = (uint32_t)(b) * BUFW;                                      \
    uint32_t ao_ = bb_ + W_AH + arow * 12 + aseg * 2;                         \
    sw[ao_ + 0] = pack_bf16(va.x, va.y);                                      \
    sw[ao_ + 1] = pack_bf16(va.z, va.w);                                      \
    uint32_t al_ = bb_ + W_AL + arow * 12 + aseg * 2;                         \
    sw[al_ + 0] = pack_bf16(va.x - bf16_rt(va.x), va.y - bf16_rt(va.y));      \
    sw[al_ + 1] = pack_bf16(va.z - bf16_rt(va.z), va.w - bf16_rt(va.w));      \
    if (tid < 256) {                                                          \
        uint32_t wo_ = bb_ + W_WH + wkp * 136 + wn4;                          \
        sw[wo_ + 0] = pack_bf16(vu.x, vv.x);                                  \
        sw[wo_ + 1] = pack_bf16(vu.y, vv.y);                                  \
        sw[wo_ + 2] = pack_bf16(vu.z, vv.z);                                  \
        sw[wo_ + 3] = pack_bf16(vu.w, vv.w);                                  \
        uint32_t wl_ = bb_ + W_WL + wkp * 136 + wn4;                          \
        sw[wl_ + 0] = pack_bf16(vu.x - bf16_rt(vu.x), vv.x - bf16_rt(vv.x));  \
        sw[wl_ + 1] = pack_bf16(vu.y - bf16_rt(vu.y), vv.y - bf16_rt(vv.y));  \
        sw[wl_ + 2] = pack_bf16(vu.z - bf16_rt(vu.z), vv.z - bf16_rt(vv.z));  \
        sw[wl_ + 3] = pack_bf16(vu.w - bf16_rt(vu.w), vv.w - bf16_rt(vv.w));  \
    }                                                                         \
} while (0)

template<int MODE>
__global__ __launch_bounds__(GT) void mma_gemm(
    const float* __restrict__ A, const float* __restrict__ Wt,
    const float* __restrict__ bias, float* __restrict__ Cout, int N)
{
    extern __shared__ uint32_t sw[];
    const float* Aptr = (MODE == 2) ? (const float*)g_o : A;

    int tid = threadIdx.x, wid = tid >> 5, lane = tid & 31;
    int g = lane >> 2, tig = lane & 3;
    int wm = wid & 3, wn = wid >> 2;          // 4x4 warps, 32x32 warp tiles
    int m0 = blockIdx.x * 128, n0 = blockIdx.y * 128;

    // loader coordinates (fixed across chunks)
    int arow = tid >> 2, aseg = tid & 3;      // A: 128 rows x 4 float4 segs
    const float* Ag = Aptr + (size_t)(m0 + arow) * 384 + aseg * 4;
    int wn4 = (tid & 31) * 4, wkp = tid >> 5; // W: threads 0-255, 8 k-pairs x 32 n-segs
    const float* Wg0 = Wt + (size_t)(2 * wkp) * N + n0 + wn4;
    const float* Wg1 = Wt + (size_t)(2 * wkp + 1) * N + n0 + wn4;

    float4 va, vu, vv;
    va = *(const float4*)(Ag);
    if (tid < 256) { vu = *(const float4*)(Wg0); vv = *(const float4*)(Wg1); }
    CONV_STORE(0);
    __syncthreads();

    float acc[2][4][4] = {};

    for (int s = 0; s < NCHK; s++) {
        if (s + 1 < NCHK) {
            int k0 = (s + 1) * KC;
            va = *(const float4*)(Ag + k0);
            if (tid < 256) {
                vu = *(const float4*)(Wg0 + (size_t)k0 * N);
                vv = *(const float4*)(Wg1 + (size_t)k0 * N);
            }
        }
        {   // compute chunk s from buffer s&1
            uint32_t base = (uint32_t)(s & 1) * BUFW;
            uint32_t ah[2][4], al[2][4], bh[4][2], bl[4][2];
            #pragma unroll
            for (int mt = 0; mt < 2; mt++) {
                int m = wm * 32 + mt * 16 + g;
                ah[mt][0] = sw[base + W_AH + m * 12 + tig];
                ah[mt][1] = sw[base + W_AH + (m + 8) * 12 + tig];
                ah[mt][2] = sw[base + W_AH + m * 12 + tig + 4];
                ah[mt][3] = sw[base + W_AH + (m + 8) * 12 + tig + 4];
                al[mt][0] = sw[base + W_AL + m * 12 + tig];
                al[mt][1] = sw[base + W_AL + (m + 8) * 12 + tig];
                al[mt][2] = sw[base + W_AL + m * 12 + tig + 4];
                al[mt][3] = sw[base + W_AL + (m + 8) * 12 + tig + 4];
            }
            #pragma unroll
            for (int nb = 0; nb < 4; nb++) {
                int n = wn * 32 + nb * 8 + g;
                bh[nb][0] = sw[base + W_WH + tig * 136 + n];
                bh[nb][1] = sw[base + W_WH + (tig + 4) * 136 + n];
                bl[nb][0] = sw[base + W_WL + tig * 136 + n];
                bl[nb][1] = sw[base + W_WL + (tig + 4) * 136 + n];
            }
            #pragma unroll
            for (int mt = 0; mt < 2; mt++)
                #pragma unroll
                for (int nb = 0; nb < 4; nb++) {
                    MMA_BF16(acc[mt][nb][0], acc[mt][nb][1], acc[mt][nb][2], acc[mt][nb][3],
                             ah[mt][0], ah[mt][1], ah[mt][2], ah[mt][3],
                             bh[nb][0], bh[nb][1]);
                    MMA_BF16(acc[mt][nb][0], acc[mt][nb][1], acc[mt][nb][2], acc[mt][nb][3],
                             al[mt][0], al[mt][1], al[mt][2], al[mt][3],
                             bh[nb][0], bh[nb][1]);
                    MMA_BF16(acc[mt][nb][0], acc[mt][nb][1], acc[mt][nb][2], acc[mt][nb][3],
                             ah[mt][0], ah[mt][1], ah[mt][2], ah[mt][3],
                             bl[nb][0], bl[nb][1]);
                }
        }
        if (s + 1 < NCHK) {
            CONV_STORE((s + 1) & 1);
            __syncthreads();
        }
    }

    // ---- epilogue: scatter per MODE (c0,c1 = cols 2tig,2tig+1; c2,c3 row+8) ----
    #pragma unroll
    for (int mt = 0; mt < 2; mt++) {
        #pragma unroll
        for (int half = 0; half < 2; half++) {
            int m = m0 + wm * 32 + mt * 16 + g + half * 8;
            int bb = m / 3136, rem = m % 3136;
            int y = rem / 56, x = rem % 56;
            int win = bb * 64 + (y / 7) * 8 + (x / 7);
            int l   = (y % 7) * 7 + (x % 7);
            #pragma unroll
            for (int nb = 0; nb < 4; nb++) {
                int col = n0 + wn * 32 + nb * 8 + tig * 2;
                float v0 = acc[mt][nb][half * 2 + 0] + bias[col];
                float v1 = acc[mt][nb][half * 2 + 1] + bias[col + 1];
                if (MODE == 0) {
                    int h = col >> 5, d = col & 31;
                    float2 p = {v0 * SCALE, v1 * SCALE};
                    *(float2*)&g_q[(((size_t)win * NH + h) * L_ + l) * HD + d] = p;
                } else if (MODE == 1) {
                    int c2 = (col < 384) ? col : col - 384;
                    int h = c2 >> 5, d = c2 & 31;
                    float* dst = (col < 384) ? g_k : g_v;
                    float2 p = {v0, v1};
                    *(float2*)&dst[(((size_t)win * NH + h) * L_ + l) * HD + d] = p;
                } else {
                    float2 p = {v0, v1};
                    *(float2*)&Cout[(size_t)m * 384 + col] = p;
                }
            }
        }
    }
}

// ---------------------------------------------------------------------------
// Fused windowed attention (unchanged from R10 pass): one block = (1 head, 4 windows)
// ---------------------------------------------------------------------------
#define WB 4
#define CP 36
#define TP 100
#define K_OFF  7056
#define V_OFF  14112
#define LO_OFF 21168
#define T_OFF  30772
#define SMEM_FLOATS (T_OFF + 169*TP)

__global__ __launch_bounds__(256) void attn_kernel(const float* __restrict__ rpe)
{
    extern __shared__ float sm[];
    float* sQ = sm;
    float* sK = sm + K_OFF;
    float* sV = sm + V_OFF;
    float* sL = sm + LO_OFF;
    float* sT = sm + T_OFF;

    int h   = blockIdx.y;
    int wg  = blockIdx.x;
    int tid = threadIdx.x;

    for (int e = tid; e < WB * 49 * 8; e += 256) {
        int w = e / 392, rem = e % 392;
        int row = rem >> 3, c4 = (rem & 7) * 4;
        size_t gb = ((((size_t)(wg * WB + w)) * NH + h) * L_ + row) * HD + c4;
        int si = w * (49 * CP) + row * CP + c4;
        *(float4*)&sQ[si] = *(const float4*)&g_q[gb];
        *(float4*)&sK[si] = *(const float4*)&g_k[gb];
        *(float4*)&sV[si] = *(const float4*)&g_v[gb];
    }
    for (int e = tid; e < 169 * 24; e += 256) {
        int row = e / 24, seg = e % 24;
        float4 v = *(const float4*)&rpe[(size_t)row * 1152 + h * 96 + seg * 4];
        if (seg < 8) { v.x *= SCALE; v.y *= SCALE; v.z *= SCALE; v.w *= SCALE; }
        *(float4*)&sT[row * TP + seg * 4] = v;
    }
    __syncthreads();

    for (int t = tid; t < 49 * 25; t += 256) {
        int i = t / 25, jp = t % 25;
        int j1 = jp, j2 = jp + 25;
        bool has2 = (jp < 24);
        int ir = i / 7, ic = i % 7;
        int b1 = ((ir - j1 / 7 + 6) * 13 + (ic - j1 % 7 + 6)) * TP;
        int b2 = ((ir - j2 / 7 + 6) * 13 + (ic - j2 % 7 + 6)) * TP;
        float accw[WB][2] = {};
        #pragma unroll
        for (int c4 = 0; c4 < 32; c4 += 4) {
            float4 qr1 = *(float4*)&sT[b1 + c4];
            float4 kr1 = *(float4*)&sT[b1 + 32 + c4];
            float4 qr2 = *(float4*)&sT[b2 + c4];
            float4 kr2 = *(float4*)&sT[b2 + 32 + c4];
            #pragma unroll
            for (int wdx = 0; wdx < WB; wdx++) {
                float4 qv = *(float4*)&sQ[wdx * (49 * CP) + i * CP + c4];
                float4 kv = *(float4*)&sK[wdx * (49 * CP) + j1 * CP + c4];
                float s = 0.f;
                s += qv.x * (kv.x + kr1.x) + kv.x * qr1.x;
                s += qv.y * (kv.y + kr1.y) + kv.y * qr1.y;
                s += qv.z * (kv.z + kr1.z) + kv.z * qr1.z;
                s += qv.w * (kv.w + kr1.w) + kv.w * qr1.w;
                accw[wdx][0] += s;
                if (has2) {
                    float4 kw = *(float4*)&sK[wdx * (49 * CP) + j2 * CP + c4];
                    float u = 0.f;
                    u += qv.x * (kw.x + kr2.x) + kw.x * qr2.x;
                    u += qv.y * (kw.y + kr2.y) + kw.y * qr2.y;
                    u += qv.z * (kw.z + kr2.z) + kw.z * qr2.z;
                    u += qv.w * (kw.w + kr2.w) + kw.w * qr2.w;
                    accw[wdx][1] += u;
                }
            }
        }
        #pragma unroll
        for (int wdx = 0; wdx < WB; wdx++) {
            sL[wdx * 2401 + i * 49 + j1] = accw[wdx][0];
            if (has2) sL[wdx * 2401 + i * 49 + j2] = accw[wdx][1];
        }
    }
    __syncthreads();

    for (int r = tid; r < WB * 49; r += 256) {
        float* row = &sL[(r / 49) * 2401 + (r % 49) * 49];
        float mx = row[0];
        #pragma unroll 7
        for (int j = 1; j < 49; j++) mx = fmaxf(mx, row[j]);
        float s = 0.f;
        #pragma unroll 7
        for (int j = 0; j < 49; j++) { float e = __expf(row[j] - mx); row[j] = e; s += e; }
        float inv = 1.f / s;
        #pragma unroll 7
        for (int j = 0; j < 49; j++) row[j] *= inv;
    }
    __syncthreads();

    for (int t = tid; t < WB * 49 * 8; t += 256) {
        int c4 = (t & 7) * 4;
        int rest = t >> 3;
        int i = rest % 49, w = rest / 49;
        int ir = i / 7, ic = i % 7;
        int base = ((ir + 6) * 13 + ic + 6) * TP + 64 + c4;
        float4 acc = {0.f, 0.f, 0.f, 0.f};
        const float* prow = &sL[w * 2401 + i * 49];
        #pragma unroll
        for (int j = 0; j < 49; j++) {
            float p = prow[j];
            float4 vv = *(float4*)&sV[w * (49 * CP) + j * CP + c4];
            float4 vr = *(float4*)&sT[base - ((j / 7) * 13 + j % 7) * TP];
            acc.x += p * (vv.x + vr.x); acc.y += p * (vv.y + vr.y);
            acc.z += p * (vv.z + vr.z); acc.w += p * (vv.w + vr.w);
        }
        int win = wg * WB + w;
        int bb = win >> 6, wi = (win >> 3) & 7, wj = win & 7;
        int y = wi * 7 + ir, x = wj * 7 + ic;
        size_t rowg = ((size_t)bb * 56 + y) * 56 + x;
        *(float4*)&g_o[rowg * 384 + h * 32 + c4] = acc;
    }
}

// ---------------------------------------------------------------------------
extern "C" void kernel_launch(void* const* d_in, const int* in_sizes, int n_in,
                              void* d_out, int out_size)
{
    const float* x   = (const float*)d_in[0];
    const float* ctx = (const float*)d_in[1];
    const float* rpe = (const float*)d_in[2];
    const float* qw  = (const float*)d_in[3];
    const float* qb  = (const float*)d_in[4];
    const float* kvw = (const float*)d_in[5];
    const float* kvb = (const float*)d_in[6];
    const float* pw  = (const float*)d_in[7];
    const float* pb  = (const float*)d_in[8];
    float* out = (float*)d_out;

    cudaFuncSetAttribute(attn_kernel, cudaFuncAttributeMaxDynamicSharedMemorySize,
                         SMEM_FLOATS * 4);

    mma_gemm<0><<<dim3(TOK / 128, 3), GT, SM_TOT>>>(x,   qw,  qb,  nullptr, 384);
    mma_gemm<1><<<dim3(TOK / 128, 6), GT, SM_TOT>>>(ctx, kvw, kvb, nullptr, 768);
    attn_kernel<<<dim3(BW / WB, NH), 256, SMEM_FLOATS * 4>>>(rpe);
    mma_gemm<2><<<dim3(TOK / 128, 3), GT, SM_TOT>>>(nullptr, pw, pb, out, 384);
}

// round 13
// speedup vs baseline: 1.9604x; 1.1160x over previous
#include <cuda_runtime.h>
#include <cuda_bf16.h>
#include <cstdint>

#define B_    32
#define HH    56
#define DIMC  384
#define NH    12
#define HD    32
#define L_    49
#define BW    2048
#define TOK   (B_*HH*HH)            // 100352
#define SCALE 0.17677669529663687f  // 32^-0.5

// Scratch (static device arrays — identical footprint to the R10/R11 passes)
__device__ float g_q[BW*NH*L_*HD];
__device__ float g_k[BW*NH*L_*HD];
__device__ float g_v[BW*NH*L_*HD];
__device__ float g_o[TOK*DIMC];

// ---------------- helpers (value-only, nothing address-taken) ----------------
__device__ __forceinline__ uint32_t pack_bf16(float lo, float hi) {
    uint32_t r;
    asm("cvt.rn.bf16x2.f32 %0, %1, %2;" : "=r"(r) : "f"(hi), "f"(lo));
    return r;
}
__device__ __forceinline__ float bf16_rt(float x) {
    return __bfloat162float(__float2bfloat16(x));
}
#define MMA_BF16(d0, d1, d2, d3, a0, a1, a2, a3, b0, b1) \
    asm volatile("mma.sync.aligned.m16n8k16.row.col.f32.bf16.bf16.f32 " \
        "{%0,%1,%2,%3}, {%4,%5,%6,%7}, {%8,%9}, {%0,%1,%2,%3};" \
        : "+f"(d0), "+f"(d1), "+f"(d2), "+f"(d3) \
        : "r"(a0), "r"(a1), "r"(a2), "r"(a3), "r"(b0), "r"(b1))

// ---------------------------------------------------------------------------
// bf16 hi/lo mma GEMM v2: C[M,N] = A[M,384] @ W[384,N] + bias
// KB=32 per pipeline stage (2 x K16 chunks): 11 syncs instead of 23, 48 MMAs
// per stage. In-register fp32->bf16 hi/lo conversion; padded-smem fragment
// extraction via plain LDS (A pitch 20 words, W pitch 136 words: load-phase
// conflict-free); vectorized conversion stores (uint2/uint4).
//  MODE 0: q proj -> g_q (window layout, xSCALE)  MODE 1: kv -> g_k/g_v
//  MODE 2: out proj -> d_out, A from g_o
// ---------------------------------------------------------------------------
#define KB 32
#define NIT 12           // 384 / 32
#define GT 512
// smem word offsets (uint32 words), per buffer:
//  A hi [128][20] (16 data + 4 pad), A lo same; W hi [16][136] (128 + 8 pad), W lo same
#define A_H 0
#define A_L 2560
#define W_H 5120
#define W_L 7296
#define BUFW 9472
#define SM_TOT (2 * BUFW * 4)   // 75,776 bytes  (> 48KB: needs FuncSetAttribute!)

#define CONV_STORE(b) do {                                                     \
    uint32_t bb_ = (uint32_t)(b) * BUFW;                                       \
    uint32_t ao_ = bb_ + A_H + arow * 20 + aseg * 2;                           \
    *(uint2*)&sw[ao_] = make_uint2(pack_bf16(va0.x, va0.y),                    \
                                   pack_bf16(va0.z, va0.w));                   \
    *(uint2*)&sw[ao_ + 8] = make_uint2(pack_bf16(va1.x, va1.y),                \
                                       pack_bf16(va1.z, va1.w));               \
    uint32_t al_ = bb_ + A_L + arow * 20 + aseg * 2;                           \
    *(uint2*)&sw[al_] = make_uint2(                                            \
        pack_bf16(va0.x - bf16_rt(va0.x), va0.y - bf16_rt(va0.y)),             \
        pack_bf16(va0.z - bf16_rt(va0.z), va0.w - bf16_rt(va0.w)));            \
    *(uint2*)&sw[al_ + 8] = make_uint2(                                        \
        pack_bf16(va1.x - bf16_rt(va1.x), va1.y - bf16_rt(va1.y)),             \
        pack_bf16(va1.z - bf16_rt(va1.z), va1.w - bf16_rt(va1.w)));            \
    uint32_t wo_ = bb_ + W_H + wkp * 136 + wn4;                                \
    *(uint4*)&sw[wo_] = make_uint4(                                            \
        pack_bf16(vu.x, vv.x), pack_bf16(vu.y, vv.y),                          \
        pack_bf16(vu.z, vv.z), pack_bf16(vu.w, vv.w));                         \
    uint32_t wl_ = bb_ + W_L + wkp * 136 + wn4;                                \
    *(uint4*)&sw[wl_] = make_uint4(                                            \
        pack_bf16(vu.x - bf16_rt(vu.x), vv.x - bf16_rt(vv.x)),                 \
        pack_bf16(vu.y - bf16_rt(vu.y), vv.y - bf16_rt(vv.y)),                 \
        pack_bf16(vu.z - bf16_rt(vu.z), vv.z - bf16_rt(vv.z)),                 \
        pack_bf16(vu.w - bf16_rt(vu.w), vv.w - bf16_rt(vv.w)));                \
} while (0)

template<int MODE>
__global__ __launch_bounds__(GT) void mma_gemm(
    const float* __restrict__ A, const float* __restrict__ Wt,
    const float* __restrict__ bias, float* __restrict__ Cout, int N)
{
    extern __shared__ uint32_t sw[];
    const float* Aptr = (MODE == 2) ? (const float*)g_o : A;

    int tid = threadIdx.x, wid = tid >> 5, lane = tid & 31;
    int g = lane >> 2, tig = lane & 3;
    int wm = wid & 3, wn = wid >> 2;          // 4x4 warps, 32x32 warp tiles
    int m0 = blockIdx.x * 128, n0 = blockIdx.y * 128;

    // loader coordinates (fixed across stages)
    int arow = tid >> 2, aseg = tid & 3;      // A: 128 rows x 4 float4 segs (16 k each chunk)
    const float* Ag = Aptr + (size_t)(m0 + arow) * 384 + aseg * 4;
    int wn4 = (tid & 31) * 4, wkp = tid >> 5; // W: 16 k-pair rows x 32 n-segs = 512 slots
    const float* Wg0 = Wt + (size_t)(2 * wkp) * N + n0 + wn4;
    const float* Wg1 = Wt + (size_t)(2 * wkp + 1) * N + n0 + wn4;

    float4 va0, va1, vu, vv;
    va0 = *(const float4*)(Ag);
    va1 = *(const float4*)(Ag + 16);
    vu  = *(const float4*)(Wg0);
    vv  = *(const float4*)(Wg1);
    CONV_STORE(0);
    __syncthreads();

    float acc[2][4][4] = {};

    for (int it = 0; it < NIT; it++) {
        if (it + 1 < NIT) {
            int k0 = (it + 1) * KB;
            va0 = *(const float4*)(Ag + k0);
            va1 = *(const float4*)(Ag + k0 + 16);
            vu  = *(const float4*)(Wg0 + (size_t)k0 * N);
            vv  = *(const float4*)(Wg1 + (size_t)k0 * N);
        }
        uint32_t base = (uint32_t)(it & 1) * BUFW;
        #pragma unroll
        for (int ks = 0; ks < 2; ks++) {
            uint32_t ab = base + ks * 8;          // word offset within A row
            uint32_t wb = base + ks * 8 * 136;    // row offset within W tile
            uint32_t ah[2][4], al[2][4], bh[4][2], bl[4][2];
            #pragma unroll
            for (int mt = 0; mt < 2; mt++) {
                int m = wm * 32 + mt * 16 + g;
                ah[mt][0] = sw[ab + A_H + m * 20 + tig];
                ah[mt][1] = sw[ab + A_H + (m + 8) * 20 + tig];
                ah[mt][2] = sw[ab + A_H + m * 20 + tig + 4];
                ah[mt][3] = sw[ab + A_H + (m + 8) * 20 + tig + 4];
                al[mt][0] = sw[ab + A_L + m * 20 + tig];
                al[mt][1] = sw[ab + A_L + (m + 8) * 20 + tig];
                al[mt][2] = sw[ab + A_L + m * 20 + tig + 4];
                al[mt][3] = sw[ab + A_L + (m + 8) * 20 + tig + 4];
            }
            #pragma unroll
            for (int nb = 0; nb < 4; nb++) {
                int n = wn * 32 + nb * 8 + g;
                bh[nb][0] = sw[wb + W_H + tig * 136 + n];
                bh[nb][1] = sw[wb + W_H + (tig + 4) * 136 + n];
                bl[nb][0] = sw[wb + W_L + tig * 136 + n];
                bl[nb][1] = sw[wb + W_L + (tig + 4) * 136 + n];
            }
            #pragma unroll
            for (int mt = 0; mt < 2; mt++)
                #pragma unroll
                for (int nb = 0; nb < 4; nb++) {
                    MMA_BF16(acc[mt][nb][0], acc[mt][nb][1], acc[mt][nb][2], acc[mt][nb][3],
                             ah[mt][0], ah[mt][1], ah[mt][2], ah[mt][3],
                             bh[nb][0], bh[nb][1]);
                    MMA_BF16(acc[mt][nb][0], acc[mt][nb][1], acc[mt][nb][2], acc[mt][nb][3],
                             al[mt][0], al[mt][1], al[mt][2], al[mt][3],
                             bh[nb][0], bh[nb][1]);
                    MMA_BF16(acc[mt][nb][0], acc[mt][nb][1], acc[mt][nb][2], acc[mt][nb][3],
                             ah[mt][0], ah[mt][1], ah[mt][2], ah[mt][3],
                             bl[nb][0], bl[nb][1]);
                }
        }
        if (it + 1 < NIT) {
            CONV_STORE((it + 1) & 1);
            __syncthreads();
        }
    }

    // ---- epilogue: scatter per MODE ----
    #pragma unroll
    for (int mt = 0; mt < 2; mt++) {
        #pragma unroll
        for (int half = 0; half < 2; half++) {
            int m = m0 + wm * 32 + mt * 16 + g + half * 8;
            int bb = m / 3136, rem = m % 3136;
            int y = rem / 56, x = rem % 56;
            int win = bb * 64 + (y / 7) * 8 + (x / 7);
            int l   = (y % 7) * 7 + (x % 7);
            #pragma unroll
            for (int nb = 0; nb < 4; nb++) {
                int col = n0 + wn * 32 + nb * 8 + tig * 2;
                float v0 = acc[mt][nb][half * 2 + 0] + bias[col];
                float v1 = acc[mt][nb][half * 2 + 1] + bias[col + 1];
                if (MODE == 0) {
                    int h = col >> 5, d = col & 31;
                    float2 p = {v0 * SCALE, v1 * SCALE};
                    *(float2*)&g_q[(((size_t)win * NH + h) * L_ + l) * HD + d] = p;
                } else if (MODE == 1) {
                    int c2 = (col < 384) ? col : col - 384;
                    int h = c2 >> 5, d = c2 & 31;
                    float* dst = (col < 384) ? g_k : g_v;
                    float2 p = {v0, v1};
                    *(float2*)&dst[(((size_t)win * NH + h) * L_ + l) * HD + d] = p;
                } else {
                    float2 p = {v0, v1};
                    *(float2*)&Cout[(size_t)m * 384 + col] = p;
                }
            }
        }
    }
}

// ---------------------------------------------------------------------------
// Fused windowed attention (unchanged from R10/R11 pass)
// ---------------------------------------------------------------------------
#define WB 4
#define CP 36
#define TP 100
#define K_OFF  7056
#define V_OFF  14112
#define LO_OFF 21168
#define T_OFF  30772
#define SMEM_FLOATS (T_OFF + 169*TP)

__global__ __launch_bounds__(256) void attn_kernel(const float* __restrict__ rpe)
{
    extern __shared__ float sm[];
    float* sQ = sm;
    float* sK = sm + K_OFF;
    float* sV = sm + V_OFF;
    float* sL = sm + LO_OFF;
    float* sT = sm + T_OFF;

    int h   = blockIdx.y;
    int wg  = blockIdx.x;
    int tid = threadIdx.x;

    for (int e = tid; e < WB * 49 * 8; e += 256) {
        int w = e / 392, rem = e % 392;
        int row = rem >> 3, c4 = (rem & 7) * 4;
        size_t gb = ((((size_t)(wg * WB + w)) * NH + h) * L_ + row) * HD + c4;
        int si = w * (49 * CP) + row * CP + c4;
        *(float4*)&sQ[si] = *(const float4*)&g_q[gb];
        *(float4*)&sK[si] = *(const float4*)&g_k[gb];
        *(float4*)&sV[si] = *(const float4*)&g_v[gb];
    }
    for (int e = tid; e < 169 * 24; e += 256) {
        int row = e / 24, seg = e % 24;
        float4 v = *(const float4*)&rpe[(size_t)row * 1152 + h * 96 + seg * 4];
        if (seg < 8) { v.x *= SCALE; v.y *= SCALE; v.z *= SCALE; v.w *= SCALE; }
        *(float4*)&sT[row * TP + seg * 4] = v;
    }
    __syncthreads();

    for (int t = tid; t < 49 * 25; t += 256) {
        int i = t / 25, jp = t % 25;
        int j1 = jp, j2 = jp + 25;
        bool has2 = (jp < 24);
        int ir = i / 7, ic = i % 7;
        int b1 = ((ir - j1 / 7 + 6) * 13 + (ic - j1 % 7 + 6)) * TP;
        int b2 = ((ir - j2 / 7 + 6) * 13 + (ic - j2 % 7 + 6)) * TP;
        float accw[WB][2] = {};
        #pragma unroll
        for (int c4 = 0; c4 < 32; c4 += 4) {
            float4 qr1 = *(float4*)&sT[b1 + c4];
            float4 kr1 = *(float4*)&sT[b1 + 32 + c4];
            float4 qr2 = *(float4*)&sT[b2 + c4];
            float4 kr2 = *(float4*)&sT[b2 + 32 + c4];
            #pragma unroll
            for (int wdx = 0; wdx < WB; wdx++) {
                float4 qv = *(float4*)&sQ[wdx * (49 * CP) + i * CP + c4];
                float4 kv = *(float4*)&sK[wdx * (49 * CP) + j1 * CP + c4];
                float s = 0.f;
                s += qv.x * (kv.x + kr1.x) + kv.x * qr1.x;
                s += qv.y * (kv.y + kr1.y) + kv.y * qr1.y;
                s += qv.z * (kv.z + kr1.z) + kv.z * qr1.z;
                s += qv.w * (kv.w + kr1.w) + kv.w * qr1.w;
                accw[wdx][0] += s;
                if (has2) {
                    float4 kw = *(float4*)&sK[wdx * (49 * CP) + j2 * CP + c4];
                    float u = 0.f;
                    u += qv.x * (kw.x + kr2.x) + kw.x * qr2.x;
                    u += qv.y * (kw.y + kr2.y) + kw.y * qr2.y;
                    u += qv.z * (kw.z + kr2.z) + kw.z * qr2.z;
                    u += qv.w * (kw.w + kr2.w) + kw.w * qr2.w;
                    accw[wdx][1] += u;
                }
            }
        }
        #pragma unroll
        for (int wdx = 0; wdx < WB; wdx++) {
            sL[wdx * 2401 + i * 49 + j1] = accw[wdx][0];
            if (has2) sL[wdx * 2401 + i * 49 + j2] = accw[wdx][1];
        }
    }
    __syncthreads();

    for (int r = tid; r < WB * 49; r += 256) {
        float* row = &sL[(r / 49) * 2401 + (r % 49) * 49];
        float mx = row[0];
        #pragma unroll 7
        for (int j = 1; j < 49; j++) mx = fmaxf(mx, row[j]);
        float s = 0.f;
        #pragma unroll 7
        for (int j = 0; j < 49; j++) { float e = __expf(row[j] - mx); row[j] = e; s += e; }
        float inv = 1.f / s;
        #pragma unroll 7
        for (int j = 0; j < 49; j++) row[j] *= inv;
    }
    __syncthreads();

    for (int t = tid; t < WB * 49 * 8; t += 256) {
        int c4 = (t & 7) * 4;
        int rest = t >> 3;
        int i = rest % 49, w = rest / 49;
        int ir = i / 7, ic = i % 7;
        int base = ((ir + 6) * 13 + ic + 6) * TP + 64 + c4;
        float4 acc = {0.f, 0.f, 0.f, 0.f};
        const float* prow = &sL[w * 2401 + i * 49];
        #pragma unroll
        for (int j = 0; j < 49; j++) {
            float p = prow[j];
            float4 vv = *(float4*)&sV[w * (49 * CP) + j * CP + c4];
            float4 vr = *(float4*)&sT[base - ((j / 7) * 13 + j % 7) * TP];
            acc.x += p * (vv.x + vr.x); acc.y += p * (vv.y + vr.y);
            acc.z += p * (vv.z + vr.z); acc.w += p * (vv.w + vr.w);
        }
        int win = wg * WB + w;
        int bb = win >> 6, wi = (win >> 3) & 7, wj = win & 7;
        int y = wi * 7 + ir, x = wj * 7 + ic;
        size_t rowg = ((size_t)bb * 56 + y) * 56 + x;
        *(float4*)&g_o[rowg * 384 + h * 32 + c4] = acc;
    }
}

// ---------------------------------------------------------------------------
extern "C" void kernel_launch(void* const* d_in, const int* in_sizes, int n_in,
                              void* d_out, int out_size)
{
    const float* x   = (const float*)d_in[0];
    const float* ctx = (const float*)d_in[1];
    const float* rpe = (const float*)d_in[2];
    const float* qw  = (const float*)d_in[3];
    const float* qb  = (const float*)d_in[4];
    const float* kvw = (const float*)d_in[5];
    const float* kvb = (const float*)d_in[6];
    const float* pw  = (const float*)d_in[7];
    const float* pb  = (const float*)d_in[8];
    float* out = (float*)d_out;

    cudaFuncSetAttribute(attn_kernel, cudaFuncAttributeMaxDynamicSharedMemorySize,
                         SMEM_FLOATS * 4);
    cudaFuncSetAttribute(mma_gemm<0>, cudaFuncAttributeMaxDynamicSharedMemorySize, SM_TOT);
    cudaFuncSetAttribute(mma_gemm<1>, cudaFuncAttributeMaxDynamicSharedMemorySize, SM_TOT);
    cudaFuncSetAttribute(mma_gemm<2>, cudaFuncAttributeMaxDynamicSharedMemorySize, SM_TOT);

    mma_gemm<0><<<dim3(TOK / 128, 3), GT, SM_TOT>>>(x,   qw,  qb,  nullptr, 384);
    mma_gemm<1><<<dim3(TOK / 128, 6), GT, SM_TOT>>>(ctx, kvw, kvb, nullptr, 768);
    attn_kernel<<<dim3(BW / WB, NH), 256, SMEM_FLOATS * 4>>>(rpe);
    mma_gemm<2><<<dim3(TOK / 128, 3), GT, SM_TOT>>>(nullptr, pw, pb, out, 384);
}

// round 14
// speedup vs baseline: 2.1606x; 1.1021x over previous
#include <cuda_runtime.h>
#include <cuda_bf16.h>
#include <cstdint>

#define B_    32
#define HH    56
#define DIMC  384
#define NH    12
#define HD    32
#define L_    49
#define BW    2048
#define TOK   (B_*HH*HH)            // 100352
#define SCALE 0.17677669529663687f  // 32^-0.5

// Scratch (static device arrays — identical footprint to the R10-R13 passes)
__device__ float g_q[BW*NH*L_*HD];
__device__ float g_k[BW*NH*L_*HD];
__device__ float g_v[BW*NH*L_*HD];
__device__ float g_o[TOK*DIMC];

// ---------------- helpers (value-only, nothing address-taken) ----------------
__device__ __forceinline__ uint32_t pack_bf16(float lo, float hi) {
    uint32_t r;
    asm("cvt.rn.bf16x2.f32 %0, %1, %2;" : "=r"(r) : "f"(hi), "f"(lo));
    return r;
}
__device__ __forceinline__ float bf16_rt(float x) {
    return __bfloat162float(__float2bfloat16(x));
}
#define MMA_BF16(d0, d1, d2, d3, a0, a1, a2, a3, b0, b1) \
    asm volatile("mma.sync.aligned.m16n8k16.row.col.f32.bf16.bf16.f32 " \
        "{%0,%1,%2,%3}, {%4,%5,%6,%7}, {%8,%9}, {%0,%1,%2,%3};" \
        : "+f"(d0), "+f"(d1), "+f"(d2), "+f"(d3) \
        : "r"(a0), "r"(a1), "r"(a2), "r"(a3), "r"(b0), "r"(b1))

// ---------------------------------------------------------------------------
// bf16 hi/lo mma GEMM v2 (unchanged from R13 pass)
// ---------------------------------------------------------------------------
#define KB 32
#define NIT 12           // 384 / 32
#define GT 512
#define A_H 0
#define A_L 2560
#define W_H 5120
#define W_L 7296
#define BUFW 9472
#define SM_TOT (2 * BUFW * 4)   // 75,776 bytes  (> 48KB: needs FuncSetAttribute!)

#define CONV_STORE(b) do {                                                     \
    uint32_t bb_ = (uint32_t)(b) * BUFW;                                       \
    uint32_t ao_ = bb_ + A_H + arow * 20 + aseg * 2;                           \
    *(uint2*)&sw[ao_] = make_uint2(pack_bf16(va0.x, va0.y),                    \
                                   pack_bf16(va0.z, va0.w));                   \
    *(uint2*)&sw[ao_ + 8] = make_uint2(pack_bf16(va1.x, va1.y),                \
                                       pack_bf16(va1.z, va1.w));               \
    uint32_t al_ = bb_ + A_L + arow * 20 + aseg * 2;                           \
    *(uint2*)&sw[al_] = make_uint2(                                            \
        pack_bf16(va0.x - bf16_rt(va0.x), va0.y - bf16_rt(va0.y)),             \
        pack_bf16(va0.z - bf16_rt(va0.z), va0.w - bf16_rt(va0.w)));            \
    *(uint2*)&sw[al_ + 8] = make_uint2(                                        \
        pack_bf16(va1.x - bf16_rt(va1.x), va1.y - bf16_rt(va1.y)),             \
        pack_bf16(va1.z - bf16_rt(va1.z), va1.w - bf16_rt(va1.w)));            \
    uint32_t wo_ = bb_ + W_H + wkp * 136 + wn4;                                \
    *(uint4*)&sw[wo_] = make_uint4(                                            \
        pack_bf16(vu.x, vv.x), pack_bf16(vu.y, vv.y),                          \
        pack_bf16(vu.z, vv.z), pack_bf16(vu.w, vv.w));                         \
    uint32_t wl_ = bb_ + W_L + wkp * 136 + wn4;                                \
    *(uint4*)&sw[wl_] = make_uint4(                                            \
        pack_bf16(vu.x - bf16_rt(vu.x), vv.x - bf16_rt(vv.x)),                 \
        pack_bf16(vu.y - bf16_rt(vu.y), vv.y - bf16_rt(vv.y)),                 \
        pack_bf16(vu.z - bf16_rt(vu.z), vv.z - bf16_rt(vv.z)),                 \
        pack_bf16(vu.w - bf16_rt(vu.w), vv.w - bf16_rt(vv.w)));                \
} while (0)

template<int MODE>
__global__ __launch_bounds__(GT) void mma_gemm(
    const float* __restrict__ A, const float* __restrict__ Wt,
    const float* __restrict__ bias, float* __restrict__ Cout, int N)
{
    extern __shared__ uint32_t sw[];
    const float* Aptr = (MODE == 2) ? (const float*)g_o : A;

    int tid = threadIdx.x, wid = tid >> 5, lane = tid & 31;
    int g = lane >> 2, tig = lane & 3;
    int wm = wid & 3, wn = wid >> 2;          // 4x4 warps, 32x32 warp tiles
    int m0 = blockIdx.x * 128, n0 = blockIdx.y * 128;

    int arow = tid >> 2, aseg = tid & 3;
    const float* Ag = Aptr + (size_t)(m0 + arow) * 384 + aseg * 4;
    int wn4 = (tid & 31) * 4, wkp = tid >> 5;
    const float* Wg0 = Wt + (size_t)(2 * wkp) * N + n0 + wn4;
    const float* Wg1 = Wt + (size_t)(2 * wkp + 1) * N + n0 + wn4;

    float4 va0, va1, vu, vv;
    va0 = *(const float4*)(Ag);
    va1 = *(const float4*)(Ag + 16);
    vu  = *(const float4*)(Wg0);
    vv  = *(const float4*)(Wg1);
    CONV_STORE(0);
    __syncthreads();

    float acc[2][4][4] = {};

    for (int it = 0; it < NIT; it++) {
        if (it + 1 < NIT) {
            int k0 = (it + 1) * KB;
            va0 = *(const float4*)(Ag + k0);
            va1 = *(const float4*)(Ag + k0 + 16);
            vu  = *(const float4*)(Wg0 + (size_t)k0 * N);
            vv  = *(const float4*)(Wg1 + (size_t)k0 * N);
        }
        uint32_t base = (uint32_t)(it & 1) * BUFW;
        #pragma unroll
        for (int ks = 0; ks < 2; ks++) {
            uint32_t ab = base + ks * 8;
            uint32_t wb = base + ks * 8 * 136;
            uint32_t ah[2][4], al[2][4], bh[4][2], bl[4][2];
            #pragma unroll
            for (int mt = 0; mt < 2; mt++) {
                int m = wm * 32 + mt * 16 + g;
                ah[mt][0] = sw[ab + A_H + m * 20 + tig];
                ah[mt][1] = sw[ab + A_H + (m + 8) * 20 + tig];
                ah[mt][2] = sw[ab + A_H + m * 20 + tig + 4];
                ah[mt][3] = sw[ab + A_H + (m + 8) * 20 + tig + 4];
                al[mt][0] = sw[ab + A_L + m * 20 + tig];
                al[mt][1] = sw[ab + A_L + (m + 8) * 20 + tig];
                al[mt][2] = sw[ab + A_L + m * 20 + tig + 4];
                al[mt][3] = sw[ab + A_L + (m + 8) * 20 + tig + 4];
            }
            #pragma unroll
            for (int nb = 0; nb < 4; nb++) {
                int n = wn * 32 + nb * 8 + g;
                bh[nb][0] = sw[wb + W_H + tig * 136 + n];
                bh[nb][1] = sw[wb + W_H + (tig + 4) * 136 + n];
                bl[nb][0] = sw[wb + W_L + tig * 136 + n];
                bl[nb][1] = sw[wb + W_L + (tig + 4) * 136 + n];
            }
            #pragma unroll
            for (int mt = 0; mt < 2; mt++)
                #pragma unroll
                for (int nb = 0; nb < 4; nb++) {
                    MMA_BF16(acc[mt][nb][0], acc[mt][nb][1], acc[mt][nb][2], acc[mt][nb][3],
                             ah[mt][0], ah[mt][1], ah[mt][2], ah[mt][3],
                             bh[nb][0], bh[nb][1]);
                    MMA_BF16(acc[mt][nb][0], acc[mt][nb][1], acc[mt][nb][2], acc[mt][nb][3],
                             al[mt][0], al[mt][1], al[mt][2], al[mt][3],
                             bh[nb][0], bh[nb][1]);
                    MMA_BF16(acc[mt][nb][0], acc[mt][nb][1], acc[mt][nb][2], acc[mt][nb][3],
                             ah[mt][0], ah[mt][1], ah[mt][2], ah[mt][3],
                             bl[nb][0], bl[nb][1]);
                }
        }
        if (it + 1 < NIT) {
            CONV_STORE((it + 1) & 1);
            __syncthreads();
        }
    }

    // ---- epilogue: scatter per MODE ----
    #pragma unroll
    for (int mt = 0; mt < 2; mt++) {
        #pragma unroll
        for (int half = 0; half < 2; half++) {
            int m = m0 + wm * 32 + mt * 16 + g + half * 8;
            int bb = m / 3136, rem = m % 3136;
            int y = rem / 56, x = rem % 56;
            int win = bb * 64 + (y / 7) * 8 + (x / 7);
            int l   = (y % 7) * 7 + (x % 7);
            #pragma unroll
            for (int nb = 0; nb < 4; nb++) {
                int col = n0 + wn * 32 + nb * 8 + tig * 2;
                float v0 = acc[mt][nb][half * 2 + 0] + bias[col];
                float v1 = acc[mt][nb][half * 2 + 1] + bias[col + 1];
                if (MODE == 0) {
                    int h = col >> 5, d = col & 31;
                    float2 p = {v0 * SCALE, v1 * SCALE};
                    *(float2*)&g_q[(((size_t)win * NH + h) * L_ + l) * HD + d] = p;
                } else if (MODE == 1) {
                    int c2 = (col < 384) ? col : col - 384;
                    int h = c2 >> 5, d = c2 & 31;
                    float* dst = (col < 384) ? g_k : g_v;
                    float2 p = {v0, v1};
                    *(float2*)&dst[(((size_t)win * NH + h) * L_ + l) * HD + d] = p;
                } else {
                    float2 p = {v0, v1};
                    *(float2*)&Cout[(size_t)m * 384 + col] = p;
                }
            }
        }
    }
}

// ---------------------------------------------------------------------------
// Fused windowed attention v3: 512 threads (16 warps/SM for latency hiding;
// R13 profile showed 8-warp occupancy starvation). Logic unchanged from the
// R10-R13 passing version; all phase loops are tid-strided.
// ---------------------------------------------------------------------------
#define WB 4
#define CP 36
#define TP 100
#define AT 512
#define K_OFF  7056
#define V_OFF  14112
#define LO_OFF 21168
#define T_OFF  30772
#define SMEM_FLOATS (T_OFF + 169*TP)

__global__ __launch_bounds__(AT) void attn_kernel(const float* __restrict__ rpe)
{
    extern __shared__ float sm[];
    float* sQ = sm;
    float* sK = sm + K_OFF;
    float* sV = sm + V_OFF;
    float* sL = sm + LO_OFF;
    float* sT = sm + T_OFF;

    int h   = blockIdx.y;
    int wg  = blockIdx.x;
    int tid = threadIdx.x;

    for (int e = tid; e < WB * 49 * 8; e += AT) {
        int w = e / 392, rem = e % 392;
        int row = rem >> 3, c4 = (rem & 7) * 4;
        size_t gb = ((((size_t)(wg * WB + w)) * NH + h) * L_ + row) * HD + c4;
        int si = w * (49 * CP) + row * CP + c4;
        *(float4*)&sQ[si] = *(const float4*)&g_q[gb];
        *(float4*)&sK[si] = *(const float4*)&g_k[gb];
        *(float4*)&sV[si] = *(const float4*)&g_v[gb];
    }
    for (int e = tid; e < 169 * 24; e += AT) {
        int row = e / 24, seg = e % 24;
        float4 v = *(const float4*)&rpe[(size_t)row * 1152 + h * 96 + seg * 4];
        if (seg < 8) { v.x *= SCALE; v.y *= SCALE; v.z *= SCALE; v.w *= SCALE; }
        *(float4*)&sT[row * TP + seg * 4] = v;
    }
    __syncthreads();

    for (int t = tid; t < 49 * 25; t += AT) {
        int i = t / 25, jp = t % 25;
        int j1 = jp, j2 = jp + 25;
        bool has2 = (jp < 24);
        int ir = i / 7, ic = i % 7;
        int b1 = ((ir - j1 / 7 + 6) * 13 + (ic - j1 % 7 + 6)) * TP;
        int b2 = ((ir - j2 / 7 + 6) * 13 + (ic - j2 % 7 + 6)) * TP;
        float accw[WB][2] = {};
        #pragma unroll
        for (int c4 = 0; c4 < 32; c4 += 4) {
            float4 qr1 = *(float4*)&sT[b1 + c4];
            float4 kr1 = *(float4*)&sT[b1 + 32 + c4];
            float4 qr2 = *(float4*)&sT[b2 + c4];
            float4 kr2 = *(float4*)&sT[b2 + 32 + c4];
            #pragma unroll
            for (int wdx = 0; wdx < WB; wdx++) {
                float4 qv = *(float4*)&sQ[wdx * (49 * CP) + i * CP + c4];
                float4 kv = *(float4*)&sK[wdx * (49 * CP) + j1 * CP + c4];
                float s = 0.f;
                s += qv.x * (kv.x + kr1.x) + kv.x * qr1.x;
                s += qv.y * (kv.y + kr1.y) + kv.y * qr1.y;
                s += qv.z * (kv.z + kr1.z) + kv.z * qr1.z;
                s += qv.w * (kv.w + kr1.w) + kv.w * qr1.w;
                accw[wdx][0] += s;
                if (has2) {
                    float4 kw = *(float4*)&sK[wdx * (49 * CP) + j2 * CP + c4];
                    float u = 0.f;
                    u += qv.x * (kw.x + kr2.x) + kw.x * qr2.x;
                    u += qv.y * (kw.y + kr2.y) + kw.y * qr2.y;
                    u += qv.z * (kw.z + kr2.z) + kw.z * qr2.z;
                    u += qv.w * (kw.w + kr2.w) + kw.w * qr2.w;
                    accw[wdx][1] += u;
                }
            }
        }
        #pragma unroll
        for (int wdx = 0; wdx < WB; wdx++) {
            sL[wdx * 2401 + i * 49 + j1] = accw[wdx][0];
            if (has2) sL[wdx * 2401 + i * 49 + j2] = accw[wdx][1];
        }
    }
    __syncthreads();

    for (int r = tid; r < WB * 49; r += AT) {
        float* row = &sL[(r / 49) * 2401 + (r % 49) * 49];
        float mx = row[0];
        #pragma unroll 7
        for (int j = 1; j < 49; j++) mx = fmaxf(mx, row[j]);
        float s = 0.f;
        #pragma unroll 7
        for (int j = 0; j < 49; j++) { float e = __expf(row[j] - mx); row[j] = e; s += e; }
        float inv = 1.f / s;
        #pragma unroll 7
        for (int j = 0; j < 49; j++) row[j] *= inv;
    }
    __syncthreads();

    for (int t = tid; t < WB * 49 * 8; t += AT) {
        int c4 = (t & 7) * 4;
        int rest = t >> 3;
        int i = rest % 49, w = rest / 49;
        int ir = i / 7, ic = i % 7;
        int base = ((ir + 6) * 13 + ic + 6) * TP + 64 + c4;
        float4 acc = {0.f, 0.f, 0.f, 0.f};
        const float* prow = &sL[w * 2401 + i * 49];
        #pragma unroll
        for (int j = 0; j < 49; j++) {
            float p = prow[j];
            float4 vv = *(float4*)&sV[w * (49 * CP) + j * CP + c4];
            float4 vr = *(float4*)&sT[base - ((j / 7) * 13 + j % 7) * TP];
            acc.x += p * (vv.x + vr.x); acc.y += p * (vv.y + vr.y);
            acc.z += p * (vv.z + vr.z); acc.w += p * (vv.w + vr.w);
        }
        int win = wg * WB + w;
        int bb = win >> 6, wi = (win >> 3) & 7, wj = win & 7;
        int y = wi * 7 + ir, x = wj * 7 + ic;
        size_t rowg = ((size_t)bb * 56 + y) * 56 + x;
        *(float4*)&g_o[rowg * 384 + h * 32 + c4] = acc;
    }
}

// ---------------------------------------------------------------------------
extern "C" void kernel_launch(void* const* d_in, const int* in_sizes, int n_in,
                              void* d_out, int out_size)
{
    const float* x   = (const float*)d_in[0];
    const float* ctx = (const float*)d_in[1];
    const float* rpe = (const float*)d_in[2];
    const float* qw  = (const float*)d_in[3];
    const float* qb  = (const float*)d_in[4];
    const float* kvw = (const float*)d_in[5];
    const float* kvb = (const float*)d_in[6];
    const float* pw  = (const float*)d_in[7];
    const float* pb  = (const float*)d_in[8];
    float* out = (float*)d_out;

    cudaFuncSetAttribute(attn_kernel, cudaFuncAttributeMaxDynamicSharedMemorySize,
                         SMEM_FLOATS * 4);
    cudaFuncSetAttribute(mma_gemm<0>, cudaFuncAttributeMaxDynamicSharedMemorySize, SM_TOT);
    cudaFuncSetAttribute(mma_gemm<1>, cudaFuncAttributeMaxDynamicSharedMemorySize, SM_TOT);
    cudaFuncSetAttribute(mma_gemm<2>, cudaFuncAttributeMaxDynamicSharedMemorySize, SM_TOT);

    mma_gemm<0><<<dim3(TOK / 128, 3), GT, SM_TOT>>>(x,   qw,  qb,  nullptr, 384);
    mma_gemm<1><<<dim3(TOK / 128, 6), GT, SM_TOT>>>(ctx, kvw, kvb, nullptr, 768);
    attn_kernel<<<dim3(BW / WB, NH), AT, SMEM_FLOATS * 4>>>(rpe);
    mma_gemm<2><<<dim3(TOK / 128, 3), GT, SM_TOT>>>(nullptr, pw, pb, out, 384);
}

// round 15
// speedup vs baseline: 2.2426x; 1.0380x over previous
#include <cuda_runtime.h>
#include <cuda_bf16.h>
#include <cstdint>

#define B_    32
#define HH    56
#define DIMC  384
#define NH    12
#define HD    32
#define L_    49
#define BW    2048
#define TOK   (B_*HH*HH)            // 100352
#define SCALE 0.17677669529663687f  // 32^-0.5

// Scratch (static device arrays — identical footprint to the R10-R14 passes)
__device__ float g_q[BW*NH*L_*HD];
__device__ float g_k[BW*NH*L_*HD];
__device__ float g_v[BW*NH*L_*HD];
__device__ float g_o[TOK*DIMC];

// ---------------- helpers (value-only, nothing address-taken) ----------------
__device__ __forceinline__ uint32_t pack_bf16(float lo, float hi) {
    uint32_t r;
    asm("cvt.rn.bf16x2.f32 %0, %1, %2;" : "=r"(r) : "f"(hi), "f"(lo));
    return r;
}
__device__ __forceinline__ float bf16_rt(float x) {
    return __bfloat162float(__float2bfloat16(x));
}
#define MMA_BF16(d0, d1, d2, d3, a0, a1, a2, a3, b0, b1) \
    asm volatile("mma.sync.aligned.m16n8k16.row.col.f32.bf16.bf16.f32 " \
        "{%0,%1,%2,%3}, {%4,%5,%6,%7}, {%8,%9}, {%0,%1,%2,%3};" \
        : "+f"(d0), "+f"(d1), "+f"(d2), "+f"(d3) \
        : "r"(a0), "r"(a1), "r"(a2), "r"(a3), "r"(b0), "r"(b1))

// ---------------------------------------------------------------------------
// bf16 hi/lo mma GEMM v3: KB=48 per pipeline stage (3 x K16 chunks):
// 7 syncs per tile (was 11), 72 MMAs per warp between barriers (was 48).
// A smem [128][28] (24 data words + 4 pad; pitch 28 = odd*4 -> conflict-free
// extraction), W smem [24][136]. In-register fp32->bf16 hi/lo conversion.
//  MODE 0: q proj -> g_q (window layout, xSCALE)  MODE 1: kv -> g_k/g_v
//  MODE 2: out proj -> d_out, A from g_o
// ---------------------------------------------------------------------------
#define KB 48
#define NIT 8            // 384 / 48
#define GT 512
// smem word offsets (uint32 words), per buffer:
#define A_H 0
#define A_L 3584
#define W_H 7168
#define W_L 10432
#define BUFW 13696
#define SM_TOT (2 * BUFW * 4)   // 109,568 bytes  (> 48KB: needs FuncSetAttribute!)

#define ST_A(off, r_, s_, v_) do {                                             \
    uint32_t o_ = (off) + (r_) * 28 + (s_) * 2;                                \
    *(uint2*)&sw[o_] = make_uint2(pack_bf16(v_.x, v_.y),                       \
                                  pack_bf16(v_.z, v_.w));                      \
} while (0)
#define ST_A_LO(off, r_, s_, v_) do {                                          \
    uint32_t o_ = (off) + (r_) * 28 + (s_) * 2;                                \
    *(uint2*)&sw[o_] = make_uint2(                                             \
        pack_bf16(v_.x - bf16_rt(v_.x), v_.y - bf16_rt(v_.y)),                 \
        pack_bf16(v_.z - bf16_rt(v_.z), v_.w - bf16_rt(v_.w)));                \
} while (0)
#define ST_W(off, kp_, n_, u_, v_) do {                                        \
    uint32_t o_ = (off) + (kp_) * 136 + (n_);                                  \
    *(uint4*)&sw[o_] = make_uint4(                                             \
        pack_bf16(u_.x, v_.x), pack_bf16(u_.y, v_.y),                          \
        pack_bf16(u_.z, v_.z), pack_bf16(u_.w, v_.w));                         \
} while (0)
#define ST_W_LO(off, kp_, n_, u_, v_) do {                                     \
    uint32_t o_ = (off) + (kp_) * 136 + (n_);                                  \
    *(uint4*)&sw[o_] = make_uint4(                                             \
        pack_bf16(u_.x - bf16_rt(u_.x), v_.x - bf16_rt(v_.x)),                 \
        pack_bf16(u_.y - bf16_rt(u_.y), v_.y - bf16_rt(v_.y)),                 \
        pack_bf16(u_.z - bf16_rt(u_.z), v_.z - bf16_rt(v_.z)),                 \
        pack_bf16(u_.w - bf16_rt(u_.w), v_.w - bf16_rt(v_.w)));                \
} while (0)

#define CONV_STORE(b) do {                                                     \
    uint32_t bb_ = (uint32_t)(b) * BUFW;                                       \
    ST_A(bb_ + A_H, ar0, as0, va0);  ST_A_LO(bb_ + A_L, ar0, as0, va0);        \
    ST_A(bb_ + A_H, ar1, as1, va1);  ST_A_LO(bb_ + A_L, ar1, as1, va1);        \
    ST_A(bb_ + A_H, ar2, as2, va2);  ST_A_LO(bb_ + A_L, ar2, as2, va2);        \
    ST_W(bb_ + W_H, wkpA, wn4, vuA, vvA);                                      \
    ST_W_LO(bb_ + W_L, wkpA, wn4, vuA, vvA);                                   \
    if (tid < 256) {                                                           \
        ST_W(bb_ + W_H, wkpB, wn4, vuB, vvB);                                  \
        ST_W_LO(bb_ + W_L, wkpB, wn4, vuB, vvB);                               \
    }                                                                          \
} while (0)

template<int MODE>
__global__ __launch_bounds__(GT) void mma_gemm(
    const float* __restrict__ A, const float* __restrict__ Wt,
    const float* __restrict__ bias, float* __restrict__ Cout, int N)
{
    extern __shared__ uint32_t sw[];
    const float* Aptr = (MODE == 2) ? (const float*)g_o : A;

    int tid = threadIdx.x, wid = tid >> 5, lane = tid & 31;
    int g = lane >> 2, tig = lane & 3;
    int wm = wid & 3, wn = wid >> 2;          // 4x4 warps, 32x32 warp tiles
    int m0 = blockIdx.x * 128, n0 = blockIdx.y * 128;

    // A loader: 3 float4 slots per thread per stage (128 rows x 12 segs)
    int ar0 = tid / 12,          as0 = tid % 12;
    int ar1 = (tid + 512) / 12,  as1 = (tid + 512) % 12;
    int ar2 = (tid + 1024) / 12, as2 = (tid + 1024) % 12;
    const float* Ag0 = Aptr + (size_t)(m0 + ar0) * 384 + as0 * 4;
    const float* Ag1 = Aptr + (size_t)(m0 + ar1) * 384 + as1 * 4;
    const float* Ag2 = Aptr + (size_t)(m0 + ar2) * 384 + as2 * 4;
    // W loader: 24 k-pairs x 32 n-segs = 768 uint4 slots (512 + 256 guarded)
    int wn4 = (tid & 31) * 4;
    int wkpA = tid >> 5;                       // 0..15
    int wkpB = 16 + (tid >> 5);                // 16..23 (tid<256)
    const float* WgA0 = Wt + (size_t)(2 * wkpA) * N + n0 + wn4;
    const float* WgA1 = WgA0 + N;
    const float* WgB0 = Wt + (size_t)(2 * wkpB) * N + n0 + wn4;
    const float* WgB1 = WgB0 + N;

    float4 va0, va1, va2, vuA, vvA, vuB, vvB;
    va0 = *(const float4*)(Ag0);
    va1 = *(const float4*)(Ag1);
    va2 = *(const float4*)(Ag2);
    vuA = *(const float4*)(WgA0);
    vvA = *(const float4*)(WgA1);
    if (tid < 256) { vuB = *(const float4*)(WgB0); vvB = *(const float4*)(WgB1); }
    CONV_STORE(0);
    __syncthreads();

    float acc[2][4][4] = {};

    for (int it = 0; it < NIT; it++) {
        if (it + 1 < NIT) {
            int k0 = (it + 1) * KB;
            va0 = *(const float4*)(Ag0 + k0);
            va1 = *(const float4*)(Ag1 + k0);
            va2 = *(const float4*)(Ag2 + k0);
            vuA = *(const float4*)(WgA0 + (size_t)k0 * N);
            vvA = *(const float4*)(WgA1 + (size_t)k0 * N);
            if (tid < 256) {
                vuB = *(const float4*)(WgB0 + (size_t)k0 * N);
                vvB = *(const float4*)(WgB1 + (size_t)k0 * N);
            }
        }
        uint32_t base = (uint32_t)(it & 1) * BUFW;
        #pragma unroll
        for (int ks = 0; ks < 3; ks++) {
            uint32_t ab = base + ks * 8;          // word offset within A row
            uint32_t wb = base + ks * 8 * 136;    // k-pair row offset within W tile
            uint32_t ah[2][4], al[2][4], bh[4][2], bl[4][2];
            #pragma unroll
            for (int mt = 0; mt < 2; mt++) {
                int m = wm * 32 + mt * 16 + g;
                ah[mt][0] = sw[ab + A_H + m * 28 + tig];
                ah[mt][1] = sw[ab + A_H + (m + 8) * 28 + tig];
                ah[mt][2] = sw[ab + A_H + m * 28 + tig + 4];
                ah[mt][3] = sw[ab + A_H + (m + 8) * 28 + tig + 4];
                al[mt][0] = sw[ab + A_L + m * 28 + tig];
                al[mt][1] = sw[ab + A_L + (m + 8) * 28 + tig];
                al[mt][2] = sw[ab + A_L + m * 28 + tig + 4];
                al[mt][3] = sw[ab + A_L + (m + 8) * 28 + tig + 4];
            }
            #pragma unroll
            for (int nb = 0; nb < 4; nb++) {
                int n = wn * 32 + nb * 8 + g;
                bh[nb][0] = sw[wb + W_H + tig * 136 + n];
                bh[nb][1] = sw[wb + W_H + (tig + 4) * 136 + n];
                bl[nb][0] = sw[wb + W_L + tig * 136 + n];
                bl[nb][1] = sw[wb + W_L + (tig + 4) * 136 + n];
            }
            #pragma unroll
            for (int mt = 0; mt < 2; mt++)
                #pragma unroll
                for (int nb = 0; nb < 4; nb++) {
                    MMA_BF16(acc[mt][nb][0], acc[mt][nb][1], acc[mt][nb][2], acc[mt][nb][3],
                             ah[mt][0], ah[mt][1], ah[mt][2], ah[mt][3],
                             bh[nb][0], bh[nb][1]);
                    MMA_BF16(acc[mt][nb][0], acc[mt][nb][1], acc[mt][nb][2], acc[mt][nb][3],
                             al[mt][0], al[mt][1], al[mt][2], al[mt][3],
                             bh[nb][0], bh[nb][1]);
                    MMA_BF16(acc[mt][nb][0], acc[mt][nb][1], acc[mt][nb][2], acc[mt][nb][3],
                             ah[mt][0], ah[mt][1], ah[mt][2], ah[mt][3],
                             bl[nb][0], bl[nb][1]);
                }
        }
        if (it + 1 < NIT) {
            CONV_STORE((it + 1) & 1);
            __syncthreads();
        }
    }

    // ---- epilogue: scatter per MODE ----
    #pragma unroll
    for (int mt = 0; mt < 2; mt++) {
        #pragma unroll
        for (int half = 0; half < 2; half++) {
            int m = m0 + wm * 32 + mt * 16 + g + half * 8;
            int bb = m / 3136, rem = m % 3136;
            int y = rem / 56, x = rem % 56;
            int win = bb * 64 + (y / 7) * 8 + (x / 7);
            int l   = (y % 7) * 7 + (x % 7);
            #pragma unroll
            for (int nb = 0; nb < 4; nb++) {
                int col = n0 + wn * 32 + nb * 8 + tig * 2;
                float v0 = acc[mt][nb][half * 2 + 0] + bias[col];
                float v1 = acc[mt][nb][half * 2 + 1] + bias[col + 1];
                if (MODE == 0) {
                    int h = col >> 5, d = col & 31;
                    float2 p = {v0 * SCALE, v1 * SCALE};
                    *(float2*)&g_q[(((size_t)win * NH + h) * L_ + l) * HD + d] = p;
                } else if (MODE == 1) {
                    int c2 = (col < 384) ? col : col - 384;
                    int h = c2 >> 5, d = c2 & 31;
                    float* dst = (col < 384) ? g_k : g_v;
                    float2 p = {v0, v1};
                    *(float2*)&dst[(((size_t)win * NH + h) * L_ + l) * HD + d] = p;
                } else {
                    float2 p = {v0, v1};
                    *(float2*)&Cout[(size_t)m * 384 + col] = p;
                }
            }
        }
    }
}

// ---------------------------------------------------------------------------
// Fused windowed attention (unchanged from R14 pass): 512 threads
// ---------------------------------------------------------------------------
#define WB 4
#define CP 36
#define TP 100
#define AT 512
#define K_OFF  7056
#define V_OFF  14112
#define LO_OFF 21168
#define T_OFF  30772
#define SMEM_FLOATS (T_OFF + 169*TP)

__global__ __launch_bounds__(AT) void attn_kernel(const float* __restrict__ rpe)
{
    extern __shared__ float sm[];
    float* sQ = sm;
    float* sK = sm + K_OFF;
    float* sV = sm + V_OFF;
    float* sL = sm + LO_OFF;
    float* sT = sm + T_OFF;

    int h   = blockIdx.y;
    int wg  = blockIdx.x;
    int tid = threadIdx.x;

    for (int e = tid; e < WB * 49 * 8; e += AT) {
        int w = e / 392, rem = e % 392;
        int row = rem >> 3, c4 = (rem & 7) * 4;
        size_t gb = ((((size_t)(wg * WB + w)) * NH + h) * L_ + row) * HD + c4;
        int si = w * (49 * CP) + row * CP + c4;
        *(float4*)&sQ[si] = *(const float4*)&g_q[gb];
        *(float4*)&sK[si] = *(const float4*)&g_k[gb];
        *(float4*)&sV[si] = *(const float4*)&g_v[gb];
    }
    for (int e = tid; e < 169 * 24; e += AT) {
        int row = e / 24, seg = e % 24;
        float4 v = *(const float4*)&rpe[(size_t)row * 1152 + h * 96 + seg * 4];
        if (seg < 8) { v.x *= SCALE; v.y *= SCALE; v.z *= SCALE; v.w *= SCALE; }
        *(float4*)&sT[row * TP + seg * 4] = v;
    }
    __syncthreads();

    for (int t = tid; t < 49 * 25; t += AT) {
        int i = t / 25, jp = t % 25;
        int j1 = jp, j2 = jp + 25;
        bool has2 = (jp < 24);
        int ir = i / 7, ic = i % 7;
        int b1 = ((ir - j1 / 7 + 6) * 13 + (ic - j1 % 7 + 6)) * TP;
        int b2 = ((ir - j2 / 7 + 6) * 13 + (ic - j2 % 7 + 6)) * TP;
        float accw[WB][2] = {};
        #pragma unroll
        for (int c4 = 0; c4 < 32; c4 += 4) {
            float4 qr1 = *(float4*)&sT[b1 + c4];
            float4 kr1 = *(float4*)&sT[b1 + 32 + c4];
            float4 qr2 = *(float4*)&sT[b2 + c4];
            float4 kr2 = *(float4*)&sT[b2 + 32 + c4];
            #pragma unroll
            for (int wdx = 0; wdx < WB; wdx++) {
                float4 qv = *(float4*)&sQ[wdx * (49 * CP) + i * CP + c4];
                float4 kv = *(float4*)&sK[wdx * (49 * CP) + j1 * CP + c4];
                float s = 0.f;
                s += qv.x * (kv.x + kr1.x) + kv.x * qr1.x;
                s += qv.y * (kv.y + kr1.y) + kv.y * qr1.y;
                s += qv.z * (kv.z + kr1.z) + kv.z * qr1.z;
                s += qv.w * (kv.w + kr1.w) + kv.w * qr1.w;
                accw[wdx][0] += s;
                if (has2) {
                    float4 kw = *(float4*)&sK[wdx * (49 * CP) + j2 * CP + c4];
                    float u = 0.f;
                    u += qv.x * (kw.x + kr2.x) + kw.x * qr2.x;
                    u += qv.y * (kw.y + kr2.y) + kw.y * qr2.y;
                    u += qv.z * (kw.z + kr2.z) + kw.z * qr2.z;
                    u += qv.w * (kw.w + kr2.w) + kw.w * qr2.w;
                    accw[wdx][1] += u;
                }
            }
        }
        #pragma unroll
        for (int wdx = 0; wdx < WB; wdx++) {
            sL[wdx * 2401 + i * 49 + j1] = accw[wdx][0];
            if (has2) sL[wdx * 2401 + i * 49 + j2] = accw[wdx][1];
        }
    }
    __syncthreads();

    for (int r = tid; r < WB * 49; r += AT) {
        float* row = &sL[(r / 49) * 2401 + (r % 49) * 49];
        float mx = row[0];
        #pragma unroll 7
        for (int j = 1; j < 49; j++) mx = fmaxf(mx, row[j]);
        float s = 0.f;
        #pragma unroll 7
        for (int j = 0; j < 49; j++) { float e = __expf(row[j] - mx); row[j] = e; s += e; }
        float inv = 1.f / s;
        #pragma unroll 7
        for (int j = 0; j < 49; j++) row[j] *= inv;
    }
    __syncthreads();

    for (int t = tid; t < WB * 49 * 8; t += AT) {
        int c4 = (t & 7) * 4;
        int rest = t >> 3;
        int i = rest % 49, w = rest / 49;
        int ir = i / 7, ic = i % 7;
        int base = ((ir + 6) * 13 + ic + 6) * TP + 64 + c4;
        float4 acc = {0.f, 0.f, 0.f, 0.f};
        const float* prow = &sL[w * 2401 + i * 49];
        #pragma unroll
        for (int j = 0; j < 49; j++) {
            float p = prow[j];
            float4 vv = *(float4*)&sV[w * (49 * CP) + j * CP + c4];
            float4 vr = *(float4*)&sT[base - ((j / 7) * 13 + j % 7) * TP];
            acc.x += p * (vv.x + vr.x); acc.y += p * (vv.y + vr.y);
            acc.z += p * (vv.z + vr.z); acc.w += p * (vv.w + vr.w);
        }
        int win = wg * WB + w;
        int bb = win >> 6, wi = (win >> 3) & 7, wj = win & 7;
        int y = wi * 7 + ir, x = wj * 7 + ic;
        size_t rowg = ((size_t)bb * 56 + y) * 56 + x;
        *(float4*)&g_o[rowg * 384 + h * 32 + c4] = acc;
    }
}

// ---------------------------------------------------------------------------
extern "C" void kernel_launch(void* const* d_in, const int* in_sizes, int n_in,
                              void* d_out, int out_size)
{
    const float* x   = (const float*)d_in[0];
    const float* ctx = (const float*)d_in[1];
    const float* rpe = (const float*)d_in[2];
    const float* qw  = (const float*)d_in[3];
    const float* qb  = (const float*)d_in[4];
    const float* kvw = (const float*)d_in[5];
    const float* kvb = (const float*)d_in[6];
    const float* pw  = (const float*)d_in[7];
    const float* pb  = (const float*)d_in[8];
    float* out = (float*)d_out;

    cudaFuncSetAttribute(attn_kernel, cudaFuncAttributeMaxDynamicSharedMemorySize,
                         SMEM_FLOATS * 4);
    cudaFuncSetAttribute(mma_gemm<0>, cudaFuncAttributeMaxDynamicSharedMemorySize, SM_TOT);
    cudaFuncSetAttribute(mma_gemm<1>, cudaFuncAttributeMaxDynamicSharedMemorySize, SM_TOT);
    cudaFuncSetAttribute(mma_gemm<2>, cudaFuncAttributeMaxDynamicSharedMemorySize, SM_TOT);

    mma_gemm<0><<<dim3(TOK / 128, 3), GT, SM_TOT>>>(x,   qw,  qb,  nullptr, 384);
    mma_gemm<1><<<dim3(TOK / 128, 6), GT, SM_TOT>>>(ctx, kvw, kvb, nullptr, 768);
    attn_kernel<<<dim3(BW / WB, NH), AT, SMEM_FLOATS * 4>>>(rpe);
    mma_gemm<2><<<dim3(TOK / 128, 3), GT, SM_TOT>>>(nullptr, pw, pb, out, 384);
}

// round 16
// speedup vs baseline: 2.3405x; 1.0437x over previous
#include <cuda_runtime.h>
#include <cuda_bf16.h>
#include <cstdint>

#define B_    32
#define HH    56
#define DIMC  384
#define NH    12
#define HD    32
#define L_    49
#define BW    2048
#define TOK   (B_*HH*HH)            // 100352
#define SCALE 0.17677669529663687f  // 32^-0.5

// Scratch (static device arrays — identical footprint to the R10-R15 passes)
__device__ float g_q[BW*NH*L_*HD];
__device__ float g_k[BW*NH*L_*HD];
__device__ float g_v[BW*NH*L_*HD];
__device__ float g_o[TOK*DIMC];

// ---------------- helpers (value-only, nothing address-taken) ----------------
__device__ __forceinline__ uint32_t pack_bf16(float lo, float hi) {
    uint32_t r;
    asm("cvt.rn.bf16x2.f32 %0, %1, %2;" : "=r"(r) : "f"(hi), "f"(lo));
    return r;
}
__device__ __forceinline__ float bf16_rt(float x) {
    return __bfloat162float(__float2bfloat16(x));
}
#define MMA_BF16(d0, d1, d2, d3, a0, a1, a2, a3, b0, b1) \
    asm volatile("mma.sync.aligned.m16n8k16.row.col.f32.bf16.bf16.f32 " \
        "{%0,%1,%2,%3}, {%4,%5,%6,%7}, {%8,%9}, {%0,%1,%2,%3};" \
        : "+f"(d0), "+f"(d1), "+f"(d2), "+f"(d3) \
        : "r"(a0), "r"(a1), "r"(a2), "r"(a3), "r"(b0), "r"(b1))

// ---------------------------------------------------------------------------
// bf16 hi/lo mma GEMM v3 (unchanged from R15 pass): KB=48, 7 syncs/tile.
// ---------------------------------------------------------------------------
#define KB 48
#define NIT 8            // 384 / 48
#define GT 512
#define A_H 0
#define A_L 3584
#define W_H 7168
#define W_L 10432
#define BUFW 13696
#define SM_TOT (2 * BUFW * 4)   // 109,568 bytes  (> 48KB: needs FuncSetAttribute!)

#define ST_A(off, r_, s_, v_) do {                                             \
    uint32_t o_ = (off) + (r_) * 28 + (s_) * 2;                                \
    *(uint2*)&sw[o_] = make_uint2(pack_bf16(v_.x, v_.y),                       \
                                  pack_bf16(v_.z, v_.w));                      \
} while (0)
#define ST_A_LO(off, r_, s_, v_) do {                                          \
    uint32_t o_ = (off) + (r_) * 28 + (s_) * 2;                                \
    *(uint2*)&sw[o_] = make_uint2(                                             \
        pack_bf16(v_.x - bf16_rt(v_.x), v_.y - bf16_rt(v_.y)),                 \
        pack_bf16(v_.z - bf16_rt(v_.z), v_.w - bf16_rt(v_.w)));                \
} while (0)
#define ST_W(off, kp_, n_, u_, v_) do {                                        \
    uint32_t o_ = (off) + (kp_) * 136 + (n_);                                  \
    *(uint4*)&sw[o_] = make_uint4(                                             \
        pack_bf16(u_.x, v_.x), pack_bf16(u_.y, v_.y),                          \
        pack_bf16(u_.z, v_.z), pack_bf16(u_.w, v_.w));                         \
} while (0)
#define ST_W_LO(off, kp_, n_, u_, v_) do {                                     \
    uint32_t o_ = (off) + (kp_) * 136 + (n_);                                  \
    *(uint4*)&sw[o_] = make_uint4(                                             \
        pack_bf16(u_.x - bf16_rt(u_.x), v_.x - bf16_rt(v_.x)),                 \
        pack_bf16(u_.y - bf16_rt(u_.y), v_.y - bf16_rt(v_.y)),                 \
        pack_bf16(u_.z - bf16_rt(u_.z), v_.z - bf16_rt(v_.z)),                 \
        pack_bf16(u_.w - bf16_rt(u_.w), v_.w - bf16_rt(v_.w)));                \
} while (0)

#define CONV_STORE(b) do {                                                     \
    uint32_t bb_ = (uint32_t)(b) * BUFW;                                       \
    ST_A(bb_ + A_H, ar0, as0, va0);  ST_A_LO(bb_ + A_L, ar0, as0, va0);        \
    ST_A(bb_ + A_H, ar1, as1, va1);  ST_A_LO(bb_ + A_L, ar1, as1, va1);        \
    ST_A(bb_ + A_H, ar2, as2, va2);  ST_A_LO(bb_ + A_L, ar2, as2, va2);        \
    ST_W(bb_ + W_H, wkpA, wn4, vuA, vvA);                                      \
    ST_W_LO(bb_ + W_L, wkpA, wn4, vuA, vvA);                                   \
    if (tid < 256) {                                                           \
        ST_W(bb_ + W_H, wkpB, wn4, vuB, vvB);                                  \
        ST_W_LO(bb_ + W_L, wkpB, wn4, vuB, vvB);                               \
    }                                                                          \
} while (0)

template<int MODE>
__global__ __launch_bounds__(GT) void mma_gemm(
    const float* __restrict__ A, const float* __restrict__ Wt,
    const float* __restrict__ bias, float* __restrict__ Cout, int N)
{
    extern __shared__ uint32_t sw[];
    const float* Aptr = (MODE == 2) ? (const float*)g_o : A;

    int tid = threadIdx.x, wid = tid >> 5, lane = tid & 31;
    int g = lane >> 2, tig = lane & 3;
    int wm = wid & 3, wn = wid >> 2;          // 4x4 warps, 32x32 warp tiles
    int m0 = blockIdx.x * 128, n0 = blockIdx.y * 128;

    int ar0 = tid / 12,          as0 = tid % 12;
    int ar1 = (tid + 512) / 12,  as1 = (tid + 512) % 12;
    int ar2 = (tid + 1024) / 12, as2 = (tid + 1024) % 12;
    const float* Ag0 = Aptr + (size_t)(m0 + ar0) * 384 + as0 * 4;
    const float* Ag1 = Aptr + (size_t)(m0 + ar1) * 384 + as1 * 4;
    const float* Ag2 = Aptr + (size_t)(m0 + ar2) * 384 + as2 * 4;
    int wn4 = (tid & 31) * 4;
    int wkpA = tid >> 5;
    int wkpB = 16 + (tid >> 5);
    const float* WgA0 = Wt + (size_t)(2 * wkpA) * N + n0 + wn4;
    const float* WgA1 = WgA0 + N;
    const float* WgB0 = Wt + (size_t)(2 * wkpB) * N + n0 + wn4;
    const float* WgB1 = WgB0 + N;

    float4 va0, va1, va2, vuA, vvA, vuB, vvB;
    va0 = *(const float4*)(Ag0);
    va1 = *(const float4*)(Ag1);
    va2 = *(const float4*)(Ag2);
    vuA = *(const float4*)(WgA0);
    vvA = *(const float4*)(WgA1);
    if (tid < 256) { vuB = *(const float4*)(WgB0); vvB = *(const float4*)(WgB1); }
    CONV_STORE(0);
    __syncthreads();

    float acc[2][4][4] = {};

    for (int it = 0; it < NIT; it++) {
        if (it + 1 < NIT) {
            int k0 = (it + 1) * KB;
            va0 = *(const float4*)(Ag0 + k0);
            va1 = *(const float4*)(Ag1 + k0);
            va2 = *(const float4*)(Ag2 + k0);
            vuA = *(const float4*)(WgA0 + (size_t)k0 * N);
            vvA = *(const float4*)(WgA1 + (size_t)k0 * N);
            if (tid < 256) {
                vuB = *(const float4*)(WgB0 + (size_t)k0 * N);
                vvB = *(const float4*)(WgB1 + (size_t)k0 * N);
            }
        }
        uint32_t base = (uint32_t)(it & 1) * BUFW;
        #pragma unroll
        for (int ks = 0; ks < 3; ks++) {
            uint32_t ab = base + ks * 8;
            uint32_t wb = base + ks * 8 * 136;
            uint32_t ah[2][4], al[2][4], bh[4][2], bl[4][2];
            #pragma unroll
            for (int mt = 0; mt < 2; mt++) {
                int m = wm * 32 + mt * 16 + g;
                ah[mt][0] = sw[ab + A_H + m * 28 + tig];
                ah[mt][1] = sw[ab + A_H + (m + 8) * 28 + tig];
                ah[mt][2] = sw[ab + A_H + m * 28 + tig + 4];
                ah[mt][3] = sw[ab + A_H + (m + 8) * 28 + tig + 4];
                al[mt][0] = sw[ab + A_L + m * 28 + tig];
                al[mt][1] = sw[ab + A_L + (m + 8) * 28 + tig];
                al[mt][2] = sw[ab + A_L + m * 28 + tig + 4];
                al[mt][3] = sw[ab + A_L + (m + 8) * 28 + tig + 4];
            }
            #pragma unroll
            for (int nb = 0; nb < 4; nb++) {
                int n = wn * 32 + nb * 8 + g;
                bh[nb][0] = sw[wb + W_H + tig * 136 + n];
                bh[nb][1] = sw[wb + W_H + (tig + 4) * 136 + n];
                bl[nb][0] = sw[wb + W_L + tig * 136 + n];
                bl[nb][1] = sw[wb + W_L + (tig + 4) * 136 + n];
            }
            #pragma unroll
            for (int mt = 0; mt < 2; mt++)
                #pragma unroll
                for (int nb = 0; nb < 4; nb++) {
                    MMA_BF16(acc[mt][nb][0], acc[mt][nb][1], acc[mt][nb][2], acc[mt][nb][3],
                             ah[mt][0], ah[mt][1], ah[mt][2], ah[mt][3],
                             bh[nb][0], bh[nb][1]);
                    MMA_BF16(acc[mt][nb][0], acc[mt][nb][1], acc[mt][nb][2], acc[mt][nb][3],
                             al[mt][0], al[mt][1], al[mt][2], al[mt][3],
                             bh[nb][0], bh[nb][1]);
                    MMA_BF16(acc[mt][nb][0], acc[mt][nb][1], acc[mt][nb][2], acc[mt][nb][3],
                             ah[mt][0], ah[mt][1], ah[mt][2], ah[mt][3],
                             bl[nb][0], bl[nb][1]);
                }
        }
        if (it + 1 < NIT) {
            CONV_STORE((it + 1) & 1);
            __syncthreads();
        }
    }

    // ---- epilogue: scatter per MODE ----
    #pragma unroll
    for (int mt = 0; mt < 2; mt++) {
        #pragma unroll
        for (int half = 0; half < 2; half++) {
            int m = m0 + wm * 32 + mt * 16 + g + half * 8;
            int bb = m / 3136, rem = m % 3136;
            int y = rem / 56, x = rem % 56;
            int win = bb * 64 + (y / 7) * 8 + (x / 7);
            int l   = (y % 7) * 7 + (x % 7);
            #pragma unroll
            for (int nb = 0; nb < 4; nb++) {
                int col = n0 + wn * 32 + nb * 8 + tig * 2;
                float v0 = acc[mt][nb][half * 2 + 0] + bias[col];
                float v1 = acc[mt][nb][half * 2 + 1] + bias[col + 1];
                if (MODE == 0) {
                    int h = col >> 5, d = col & 31;
                    float2 p = {v0 * SCALE, v1 * SCALE};
                    *(float2*)&g_q[(((size_t)win * NH + h) * L_ + l) * HD + d] = p;
                } else if (MODE == 1) {
                    int c2 = (col < 384) ? col : col - 384;
                    int h = c2 >> 5, d = c2 & 31;
                    float* dst = (col < 384) ? g_k : g_v;
                    float2 p = {v0, v1};
                    *(float2*)&dst[(((size_t)win * NH + h) * L_ + l) * HD + d] = p;
                } else {
                    float2 p = {v0, v1};
                    *(float2*)&Cout[(size_t)m * 384 + col] = p;
                }
            }
        }
    }
}

// ---------------------------------------------------------------------------
// Fused windowed attention v4: 512 threads. Phase C re-owned as (i, c4) x
// all-4-windows so the vr table read (the only non-broadcast LDS in the j
// loop) is fetched once instead of 4x. Phases A/B unchanged from R15 pass.
// ---------------------------------------------------------------------------
#define WB 4
#define CP 36
#define TP 100
#define AT 512
#define K_OFF  7056
#define V_OFF  14112
#define LO_OFF 21168
#define T_OFF  30772
#define SMEM_FLOATS (T_OFF + 169*TP)

__global__ __launch_bounds__(AT) void attn_kernel(const float* __restrict__ rpe)
{
    extern __shared__ float sm[];
    float* sQ = sm;
    float* sK = sm + K_OFF;
    float* sV = sm + V_OFF;
    float* sL = sm + LO_OFF;
    float* sT = sm + T_OFF;

    int h   = blockIdx.y;
    int wg  = blockIdx.x;
    int tid = threadIdx.x;

    for (int e = tid; e < WB * 49 * 8; e += AT) {
        int w = e / 392, rem = e % 392;
        int row = rem >> 3, c4 = (rem & 7) * 4;
        size_t gb = ((((size_t)(wg * WB + w)) * NH + h) * L_ + row) * HD + c4;
        int si = w * (49 * CP) + row * CP + c4;
        *(float4*)&sQ[si] = *(const float4*)&g_q[gb];
        *(float4*)&sK[si] = *(const float4*)&g_k[gb];
        *(float4*)&sV[si] = *(const float4*)&g_v[gb];
    }
    for (int e = tid; e < 169 * 24; e += AT) {
        int row = e / 24, seg = e % 24;
        float4 v = *(const float4*)&rpe[(size_t)row * 1152 + h * 96 + seg * 4];
        if (seg < 8) { v.x *= SCALE; v.y *= SCALE; v.z *= SCALE; v.w *= SCALE; }
        *(float4*)&sT[row * TP + seg * 4] = v;
    }
    __syncthreads();

    // ---- Phase A (unchanged) ----
    for (int t = tid; t < 49 * 25; t += AT) {
        int i = t / 25, jp = t % 25;
        int j1 = jp, j2 = jp + 25;
        bool has2 = (jp < 24);
        int ir = i / 7, ic = i % 7;
        int b1 = ((ir - j1 / 7 + 6) * 13 + (ic - j1 % 7 + 6)) * TP;
        int b2 = ((ir - j2 / 7 + 6) * 13 + (ic - j2 % 7 + 6)) * TP;
        float accw[WB][2] = {};
        #pragma unroll
        for (int c4 = 0; c4 < 32; c4 += 4) {
            float4 qr1 = *(float4*)&sT[b1 + c4];
            float4 kr1 = *(float4*)&sT[b1 + 32 + c4];
            float4 qr2 = *(float4*)&sT[b2 + c4];
            float4 kr2 = *(float4*)&sT[b2 + 32 + c4];
            #pragma unroll
            for (int wdx = 0; wdx < WB; wdx++) {
                float4 qv = *(float4*)&sQ[wdx * (49 * CP) + i * CP + c4];
                float4 kv = *(float4*)&sK[wdx * (49 * CP) + j1 * CP + c4];
                float s = 0.f;
                s += qv.x * (kv.x + kr1.x) + kv.x * qr1.x;
                s += qv.y * (kv.y + kr1.y) + kv.y * qr1.y;
                s += qv.z * (kv.z + kr1.z) + kv.z * qr1.z;
                s += qv.w * (kv.w + kr1.w) + kv.w * qr1.w;
                accw[wdx][0] += s;
                if (has2) {
                    float4 kw = *(float4*)&sK[wdx * (49 * CP) + j2 * CP + c4];
                    float u = 0.f;
                    u += qv.x * (kw.x + kr2.x) + kw.x * qr2.x;
                    u += qv.y * (kw.y + kr2.y) + kw.y * qr2.y;
                    u += qv.z * (kw.z + kr2.z) + kw.z * qr2.z;
                    u += qv.w * (kw.w + kr2.w) + kw.w * qr2.w;
                    accw[wdx][1] += u;
                }
            }
        }
        #pragma unroll
        for (int wdx = 0; wdx < WB; wdx++) {
            sL[wdx * 2401 + i * 49 + j1] = accw[wdx][0];
            if (has2) sL[wdx * 2401 + i * 49 + j2] = accw[wdx][1];
        }
    }
    __syncthreads();

    // ---- Phase B (unchanged) ----
    for (int r = tid; r < WB * 49; r += AT) {
        float* row = &sL[(r / 49) * 2401 + (r % 49) * 49];
        float mx = row[0];
        #pragma unroll 7
        for (int j = 1; j < 49; j++) mx = fmaxf(mx, row[j]);
        float s = 0.f;
        #pragma unroll 7
        for (int j = 0; j < 49; j++) { float e = __expf(row[j] - mx); row[j] = e; s += e; }
        float inv = 1.f / s;
        #pragma unroll 7
        for (int j = 0; j < 49; j++) row[j] *= inv;
    }
    __syncthreads();

    // ---- Phase C v2: unit = (i, c4), all 4 windows in registers ----
    for (int t = tid; t < 49 * 8; t += AT) {
        int i = t >> 3, c4 = (t & 7) * 4;
        int ir = i / 7, ic = i % 7;
        int base = ((ir + 6) * 13 + ic + 6) * TP + 64 + c4;
        float4 aw0 = {0.f, 0.f, 0.f, 0.f};
        float4 aw1 = aw0, aw2 = aw0, aw3 = aw0;
        const float* p0 = &sL[0 * 2401 + i * 49];
        const float* p1 = &sL[1 * 2401 + i * 49];
        const float* p2 = &sL[2 * 2401 + i * 49];
        const float* p3 = &sL[3 * 2401 + i * 49];
        #pragma unroll 7
        for (int j = 0; j < 49; j++) {
            float4 vr = *(float4*)&sT[base - ((j / 7) * 13 + j % 7) * TP];
            float4 v0 = *(float4*)&sV[0 * (49 * CP) + j * CP + c4];
            float4 v1 = *(float4*)&sV[1 * (49 * CP) + j * CP + c4];
            float4 v2 = *(float4*)&sV[2 * (49 * CP) + j * CP + c4];
            float4 v3 = *(float4*)&sV[3 * (49 * CP) + j * CP + c4];
            float q0 = p0[j], q1 = p1[j], q2 = p2[j], q3 = p3[j];
            aw0.x += q0 * (v0.x + vr.x); aw0.y += q0 * (v0.y + vr.y);
            aw0.z += q0 * (v0.z + vr.z); aw0.w += q0 * (v0.w + vr.w);
            aw1.x += q1 * (v1.x + vr.x); aw1.y += q1 * (v1.y + vr.y);
            aw1.z += q1 * (v1.z + vr.z); aw1.w += q1 * (v1.w + vr.w);
            aw2.x += q2 * (v2.x + vr.x); aw2.y += q2 * (v2.y + vr.y);
            aw2.z += q2 * (v2.z + vr.z); aw2.w += q2 * (v2.w + vr.w);
            aw3.x += q3 * (v3.x + vr.x); aw3.y += q3 * (v3.y + vr.y);
            aw3.z += q3 * (v3.z + vr.z); aw3.w += q3 * (v3.w + vr.w);
        }
        int wbse = wg * WB;
        {
            int win = wbse + 0;
            int bb = win >> 6, wi = (win >> 3) & 7, wj = win & 7;
            size_t rowg = ((size_t)bb * 56 + wi * 7 + ir) * 56 + wj * 7 + ic;
            *(float4*)&g_o[rowg * 384 + h * 32 + c4] = aw0;
        }
        {
            int win = wbse + 1;
            int bb = win >> 6, wi = (win >> 3) & 7, wj = win & 7;
            size_t rowg = ((size_t)bb * 56 + wi * 7 + ir) * 56 + wj * 7 + ic;
            *(float4*)&g_o[rowg * 384 + h * 32 + c4] = aw1;
        }
        {
            int win = wbse + 2;
            int bb = win >> 6, wi = (win >> 3) & 7, wj = win & 7;
            size_t rowg = ((size_t)bb * 56 + wi * 7 + ir) * 56 + wj * 7 + ic;
            *(float4*)&g_o[rowg * 384 + h * 32 + c4] = aw2;
        }
        {
            int win = wbse + 3;
            int bb = win >> 6, wi = (win >> 3) & 7, wj = win & 7;
            size_t rowg = ((size_t)bb * 56 + wi * 7 + ir) * 56 + wj * 7 + ic;
            *(float4*)&g_o[rowg * 384 + h * 32 + c4] = aw3;
        }
    }
}

// ---------------------------------------------------------------------------
extern "C" void kernel_launch(void* const* d_in, const int* in_sizes, int n_in,
                              void* d_out, int out_size)
{
    const float* x   = (const float*)d_in[0];
    const float* ctx = (const float*)d_in[1];
    const float* rpe = (const float*)d_in[2];
    const float* qw  = (const float*)d_in[3];
    const float* qb  = (const float*)d_in[4];
    const float* kvw = (const float*)d_in[5];
    const float* kvb = (const float*)d_in[6];
    const float* pw  = (const float*)d_in[7];
    const float* pb  = (const float*)d_in[8];
    float* out = (float*)d_out;

    cudaFuncSetAttribute(attn_kernel, cudaFuncAttributeMaxDynamicSharedMemorySize,
                         SMEM_FLOATS * 4);
    cudaFuncSetAttribute(mma_gemm<0>, cudaFuncAttributeMaxDynamicSharedMemorySize, SM_TOT);
    cudaFuncSetAttribute(mma_gemm<1>, cudaFuncAttributeMaxDynamicSharedMemorySize, SM_TOT);
    cudaFuncSetAttribute(mma_gemm<2>, cudaFuncAttributeMaxDynamicSharedMemorySize, SM_TOT);

    mma_gemm<0><<<dim3(TOK / 128, 3), GT, SM_TOT>>>(x,   qw,  qb,  nullptr, 384);
    mma_gemm<1><<<dim3(TOK / 128, 6), GT, SM_TOT>>>(ctx, kvw, kvb, nullptr, 768);
    attn_kernel<<<dim3(BW / WB, NH), AT, SMEM_FLOATS * 4>>>(rpe);
    mma_gemm<2><<<dim3(TOK / 128, 3), GT, SM_TOT>>>(nullptr, pw, pb, out, 384);
}